// round 9
// baseline (speedup 1.0000x reference)
#include <cuda_runtime.h>
#include <cuda_bf16.h>
#include <cuda_fp16.h>
#include <cuda_fp8.h>
#include <cstdio>
#include <cstdint>

#define NND 20
#define CHN 512
#define HH  64
#define WW  64
#define HW  4096
#define CHW 2097152   // 512*64*64

// Big scratch: [V:1][Gr,Gu,Go:3][cs:1][rh:1][U:1][O:1][h:20][R:20] = 48 planes
__device__ float g_buf[48ll * CHW];
__device__ float g_b[NND * CHN];            // per-node channel bias (lang part + mconv_b)
__device__ float g_t[3 * NND * 9 * CHN];    // per-gate per-node per-tap constant vectors
__device__ int   g_childcount[NND];
__device__ int   g_child[NND * NND];

// weights: [part(6)][tap(9)][o(512)][ci(512)]
// parts: 0=reset_x 1=reset_h 2=update_x 3=update_h 4=output_x 5=output_h
__device__ __half   g_w16[6ll * 9 * 512 * 512];  // wh (fp16)
__device__ uint8_t  g_w8a[6ll * 9 * 512 * 512];  // e4m3(wh * 16)
__device__ uint8_t  g_w8b[6ll * 9 * 512 * 512];  // e4m3(wl * 4096)
// transposed+split inputs: 3 tensors (A,B,C), each [px(4096)][ci(512)]
__device__ __half   g_x16[3ll * CHW];            // xh
__device__ uint8_t  g_x8a[3ll * CHW];            // e4m3(xh * 16)
__device__ uint8_t  g_x8b[3ll * CHW];            // e4m3(xl * 4096)

__device__ __forceinline__ float sigm(float v) { return 1.f / (1.f + expf(-v)); }

// ======================= low-level helpers (sm_100-safe) ====================
__device__ __forceinline__ uint32_t smem_u32(const void* p) {
    uint32_t a;
    asm("{ .reg .u64 t; cvta.to.shared.u64 t, %1; cvt.u32.u64 %0, t; }"
        : "=r"(a) : "l"(p));
    return a;
}
__device__ __forceinline__ void cp16(uint32_t dst, const void* src, uint32_t ssz) {
    asm volatile("cp.async.cg.shared.global [%0], [%1], 16, %2;"
        :: "r"(dst), "l"(src), "r"(ssz) : "memory");
}
__device__ __forceinline__ void ldm4(uint32_t* r, uint32_t addr) {
    asm volatile("ldmatrix.sync.aligned.m8n8.x4.shared.b16 {%0,%1,%2,%3}, [%4];"
        : "=r"(r[0]), "=r"(r[1]), "=r"(r[2]), "=r"(r[3]) : "r"(addr));
}
// fp16 m16n8k16, fp32 accum
__device__ __forceinline__ void mma_h(float* c, const uint32_t* a,
                                      uint32_t b0, uint32_t b1) {
    asm volatile(
        "mma.sync.aligned.m16n8k16.row.col.f32.f16.f16.f32 "
        "{%0,%1,%2,%3}, {%4,%5,%6,%7}, {%8,%9}, {%0,%1,%2,%3};"
        : "+f"(c[0]), "+f"(c[1]), "+f"(c[2]), "+f"(c[3])
        : "r"(a[0]), "r"(a[1]), "r"(a[2]), "r"(a[3]), "r"(b0), "r"(b1));
}
// e4m3 m16n8k32, fp32 accum
__device__ __forceinline__ void mma_q(float* c, const uint32_t* a,
                                      uint32_t b0, uint32_t b1) {
    asm volatile(
        "mma.sync.aligned.m16n8k32.row.col.f32.e4m3.e4m3.f32 "
        "{%0,%1,%2,%3}, {%4,%5,%6,%7}, {%8,%9}, {%0,%1,%2,%3};"
        : "+f"(c[0]), "+f"(c[1]), "+f"(c[2]), "+f"(c[3])
        : "r"(a[0]), "r"(a[1]), "r"(a[2]), "r"(a[3]), "r"(b0), "r"(b1));
}
#define SWZ(off) ((off) ^ (((off) >> 3) & 0x70))
// fp8 tile: 128 logical rows x 64B packed as 64 phys rows x 128B
#define PHYS8(r, sg) ((((r) >> 1) << 7) + (((r) & 1) << 6) + ((sg) << 4))

__device__ __forceinline__ uint8_t f2q(float v) {
    return (uint8_t)__nv_cvt_float_to_fp8(v, __NV_SATFINITE, __NV_E4M3);
}

// ---------------------------------------------------------------------------
// Tree prep
// ---------------------------------------------------------------------------
__global__ void prep_kernel(const int* __restrict__ adj) {
    int n = threadIdx.x;
    if (n < NND) {
        int cnt = 0;
        for (int k = 0; k < NND; k++)
            if (adj[n * NND + k] != 0) g_child[n * NND + cnt++] = k;
        g_childcount[n] = cnt;
    }
}

// ---------------------------------------------------------------------------
// b[n][o] = mconv_b[o] + sum_i mconv_w[o, 512+i] * lang[n, i]
// ---------------------------------------------------------------------------
__global__ void langbias_kernel(const float* __restrict__ lang,
                                const float* __restrict__ mw,
                                const float* __restrict__ mb) {
    int idx = blockIdx.x * 256 + threadIdx.x;
    if (idx >= NND * CHN) return;
    int n = idx / CHN, o = idx - n * CHN;
    const float* wp = mw + o * 812 + 512;
    const float* lp = lang + n * 300;
    float acc = mb[o];
    for (int i = 0; i < 300; i++) acc += wp[i] * lp[i];
    g_b[idx] = acc;
}

// ---------------------------------------------------------------------------
// t[g][n][tap][o] = sum_{i<512} Wg_x[o,i,tap] * b[n][i]
// ---------------------------------------------------------------------------
__global__ void tapconst_kernel(const float* __restrict__ rw,
                                const float* __restrict__ uw,
                                const float* __restrict__ ow) {
    __shared__ float bs[NND * CHN];  // 40KB
    int tid = threadIdx.x;
    for (int idx = tid; idx < NND * CHN; idx += 256) bs[idx] = g_b[idx];
    __syncthreads();
    int gidx = blockIdx.x * 256 + tid;
    int o   = gidx & (CHN - 1);
    int tap = (gidx >> 9) % 9;
    int g   = gidx / (CHN * 9);
    const float* w = (g == 0) ? rw : (g == 1) ? uw : ow;
    const float* wp = w + o * 9216 + tap;
    float acc[NND];
#pragma unroll
    for (int n = 0; n < NND; n++) acc[n] = 0.f;
    for (int i = 0; i < CHN; i++) {
        float wv = wp[i * 9];
#pragma unroll
        for (int n = 0; n < NND; n++) acc[n] += wv * bs[n * CHN + i];
    }
#pragma unroll
    for (int n = 0; n < NND; n++)
        g_t[((g * NND + n) * 9 + tap) * CHN + o] = acc[n];
}

// ---------------------------------------------------------------------------
// Weight split/quant into g_w16 / g_w8a / g_w8b  [part][tap][o][ci]
// ---------------------------------------------------------------------------
__global__ void wprep_kernel(const float* __restrict__ rw,
                             const float* __restrict__ uw,
                             const float* __restrict__ ow) {
    int idx = blockIdx.x * 256 + threadIdx.x;
    if (idx >= 6 * 9 * 512 * 512) return;
    int ci = idx & 511;
    int t  = idx >> 9;
    int o  = t & 511; t >>= 9;
    int tap = t % 9;
    int part = t / 9;
    const float* w = (part < 2) ? rw : (part < 4) ? uw : ow;
    int coff = (part & 1) << 9;
    float v = w[(size_t)o * 9216 + (size_t)(coff + ci) * 9 + tap];
    __half h = __float2half(v);
    float hf = __half2float(h);
    float l  = v - hf;
    size_t base = ((((size_t)part * 9 + tap) * 512 + o) << 9) + ci;
    g_w16[base] = h;
    g_w8a[base] = f2q(hf * 16.f);
    g_w8b[base] = f2q(l * 4096.f);
}

// ---------------------------------------------------------------------------
// Input transpose + split: src[ci][px] fp32 -> x16/x8a/x8b [px][ci]
// ---------------------------------------------------------------------------
__device__ __forceinline__ void split_emit(float v, size_t o,
                                           __half* x16, uint8_t* x8a,
                                           uint8_t* x8b) {
    __half h = __float2half(v);
    float hf = __half2float(h);
    x16[o] = h;
    x8a[o] = f2q(hf * 16.f);
    x8b[o] = f2q((v - hf) * 4096.f);
}
__device__ __forceinline__ void split_t_body(const float* __restrict__ src,
                                             __half* x16, uint8_t* x8a,
                                             uint8_t* x8b) {
    __shared__ float tile[32][33];
    int tx = threadIdx.x & 31, ty = threadIdx.x >> 5;   // 256 threads
    int p0 = blockIdx.x << 5, ci0 = blockIdx.y << 5;
#pragma unroll
    for (int r = 0; r < 4; r++)
        tile[ty + r * 8][tx] = src[(size_t)(ci0 + ty + r * 8) * HW + p0 + tx];
    __syncthreads();
#pragma unroll
    for (int r = 0; r < 4; r++) {
        int p = p0 + ty + r * 8, ci = ci0 + tx;
        split_emit(tile[tx][ty + r * 8], (size_t)p * 512 + ci, x16, x8a, x8b);
    }
}
__global__ void split_t_kernel(const float* __restrict__ src,
                               __half* x16, uint8_t* x8a, uint8_t* x8b,
                               int flag_n) {
    if (flag_n >= 0 && g_childcount[flag_n] == 0) return;
    split_t_body(src, x16, x8a, x8b);
}
// dual: z=0 src0->tensor0, z=1 src1->tensor1
__global__ void split_t_dual_kernel(const float* __restrict__ src0,
                                    __half* x160, uint8_t* x8a0, uint8_t* x8b0,
                                    const float* __restrict__ src1,
                                    __half* x161, uint8_t* x8a1, uint8_t* x8b1,
                                    int flag_n) {
    if (flag_n >= 0 && g_childcount[flag_n] == 0) return;
    if (blockIdx.z == 0) split_t_body(src0, x160, x8a0, x8b0);
    else                 split_t_body(src1, x161, x8a1, x8b1);
}

// ---------------------------------------------------------------------------
// GEMM: V = vis @ W_vis  (1x1 conv), fp32
// ---------------------------------------------------------------------------
__global__ __launch_bounds__(128) void gemm_kernel(
    const float* __restrict__ in, const float* __restrict__ w,
    int ldw, int K, float* __restrict__ out) {
    __shared__ float xs[8 * 128];
    __shared__ float wsm[8 * 65];
    int pB  = blockIdx.x * 128;
    int coB = blockIdx.y * 64;
    int tid = threadIdx.x;
    int pxg = tid & 15, cog = tid >> 4;
    float acc[8][8];
#pragma unroll
    for (int a = 0; a < 8; a++)
#pragma unroll
        for (int b = 0; b < 8; b++) acc[a][b] = 0.f;

    for (int kb = 0; kb < K; kb += 8) {
        __syncthreads();
        for (int idx = tid; idx < 1024; idx += 128) {
            int i = idx >> 7, p = idx & 127;
            xs[idx] = in[(kb + i) * HW + pB + p];
        }
        for (int idx = tid; idx < 512; idx += 128) {
            int co = idx >> 3, i = idx & 7;
            wsm[i * 65 + co] = w[(coB + co) * ldw + kb + i];
        }
        __syncthreads();
#pragma unroll
        for (int i = 0; i < 8; i++) {
            float xv[8], wv[8];
#pragma unroll
            for (int v = 0; v < 8; v++) xv[v] = xs[i * 128 + pxg + 16 * v];
#pragma unroll
            for (int u = 0; u < 8; u++) wv[u] = wsm[i * 65 + u * 8 + cog];
#pragma unroll
            for (int u = 0; u < 8; u++)
#pragma unroll
                for (int v = 0; v < 8; v++)
                    acc[u][v] = fmaf(wv[u], xv[v], acc[u][v]);
        }
    }
#pragma unroll
    for (int u = 0; u < 8; u++) {
        float* op = out + (coB + u * 8 + cog) * HW + pB + pxg;
#pragma unroll
        for (int v = 0; v < 8; v++) op[16 * v] = acc[u][v];
    }
}

// ---------------------------------------------------------------------------
// mma.sync implicit-GEMM 3x3 conv, fp16 hi term + fp8 correction terms.
// CTA: 128 thr = 4 warps (2m x 2n). Tile 128 co x 128 px, warp tile 64x64.
// 144 stages: [0,72) fp16 xh*wh; [72,144) fp8 (xl*wh + xh*wl) at scale 2^16.
// 3-slot cp.async pipeline (32KB slots), one __syncthreads per stage.
// ---------------------------------------------------------------------------
#define CONV_SMEM 98304   // 3 x 32KB

__device__ __forceinline__ void conv_issue_stage(
    int s, uint32_t sA, int tid, int yB, int coB, int part,
    const __half* x16, const uint8_t* x8a, const uint8_t* x8b) {
    uint32_t slot = sA + (s % 3) * 32768;
    if (s < 72) {
        int tap = s >> 3, cb = (s & 7) << 6;
        int ky = tap / 3, kx = tap - ky * 3;
        const __half* wsrc =
            g_w16 + ((((size_t)part * 9 + tap) * 512 + coB) << 9) + cb;
#pragma unroll
        for (int it = 0; it < 8; it++) {
            int i = tid + it * 128;
            int o = i >> 3, q = i & 7;
            cp16(slot + SWZ(o * 128 + q * 16),
                 wsrc + ((size_t)o << 9) + q * 8, 16u);
        }
        const __half* xs = x16 + cb;
#pragma unroll
        for (int it = 0; it < 8; it++) {
            int i = tid + it * 128;
            int j = i >> 3, q = i & 7;
            int jr = j >> 6;
            int sx = (j & 63) + kx - 1;
            int sy = yB + jr + ky - 1;
            bool ok = ((unsigned)sy < 64u) && ((unsigned)sx < 64u);
            int px = ok ? ((sy << 6) + sx) : 0;
            cp16(slot + 16384 + SWZ(j * 128 + q * 16),
                 xs + ((size_t)px << 9) + q * 8, ok ? 16u : 0u);
        }
    } else {
        int s2 = s - 72;
        int tap = s2 >> 3, cb = (s2 & 7) << 6;
        int ky = tap / 3, kx = tap - ky * 3;
        size_t wb = ((((size_t)part * 9 + tap) * 512 + coB) << 9) + cb;
        const uint8_t* wa = g_w8a + wb;
        const uint8_t* wl = g_w8b + wb;
#pragma unroll
        for (int it = 0; it < 4; it++) {
            int i = tid + it * 128;
            int r = i >> 2, q = i & 3;
            uint32_t d = SWZ(PHYS8(r, q));
            cp16(slot + d,        wa + ((size_t)r << 9) + q * 16, 16u);
            cp16(slot + 8192 + d, wl + ((size_t)r << 9) + q * 16, 16u);
        }
        const uint8_t* xl = x8b + cb;   // term2 B operand: xl*4096
        const uint8_t* xh = x8a + cb;   // term3 B operand: xh*16
#pragma unroll
        for (int it = 0; it < 4; it++) {
            int i = tid + it * 128;
            int j = i >> 2, q = i & 3;
            int jr = j >> 6;
            int sx = (j & 63) + kx - 1;
            int sy = yB + jr + ky - 1;
            bool ok = ((unsigned)sy < 64u) && ((unsigned)sx < 64u);
            int px = ok ? ((sy << 6) + sx) : 0;
            uint32_t d = SWZ(PHYS8(j, q));
            cp16(slot + 16384 + d, xl + ((size_t)px << 9) + q * 16, ok ? 16u : 0u);
            cp16(slot + 24576 + d, xh + ((size_t)px << 9) + q * 16, ok ? 16u : 0u);
        }
    }
    asm volatile("cp.async.commit_group;" ::: "memory");
}

__device__ __forceinline__ void conv_mma_body(
    const __half* __restrict__ x16, const uint8_t* __restrict__ x8a,
    const uint8_t* __restrict__ x8b, int part,
    float* __restrict__ out, char* smem) {
    uint32_t sA = smem_u32(smem);
    int tid = threadIdx.x;
    int wid = tid >> 5, lane = tid & 31;
    int yB  = blockIdx.x * 2;
    int pB  = blockIdx.x * 128;
    int coB = blockIdx.y * 128;
    int wm = wid >> 1;           // 0..1 -> co + 64*wm
    int wn = wid & 1;            // 0..1 -> px + 64*wn

    float acc[4][8][4];          // [m-frag 16][n-frag 8][c]
#pragma unroll
    for (int a = 0; a < 4; a++)
#pragma unroll
        for (int b = 0; b < 8; b++)
#pragma unroll
            for (int c = 0; c < 4; c++) acc[a][b][c] = 0.f;

    conv_issue_stage(0, sA, tid, yB, coB, part, x16, x8a, x8b);
    conv_issue_stage(1, sA, tid, yB, coB, part, x16, x8a, x8b);

    for (int s = 0; s < 144; s++) {
        asm volatile("cp.async.wait_group 1;" ::: "memory");
        __syncthreads();
        if (s + 2 < 144)
            conv_issue_stage(s + 2, sA, tid, yB, coB, part, x16, x8a, x8b);
        if (s == 72) {  // switch to fp8 scale 2^16
#pragma unroll
            for (int a = 0; a < 4; a++)
#pragma unroll
                for (int b = 0; b < 8; b++)
#pragma unroll
                    for (int c = 0; c < 4; c++) acc[a][b][c] *= 65536.f;
        }
        uint32_t Ab = sA + (s % 3) * 32768;
        if (s < 72) {
            uint32_t Bb = Ab + 16384;
#pragma unroll
            for (int ks = 0; ks < 4; ks++) {
                uint32_t afr[4][4];
#pragma unroll
                for (int mi = 0; mi < 4; mi++) {
                    int row = wm * 64 + mi * 16 + (lane & 15);
                    int k16 = ks * 2 + (lane >> 4);
                    ldm4(afr[mi], Ab + SWZ(row * 128 + k16 * 16));
                }
                uint32_t bfr[4][4];
#pragma unroll
                for (int ng = 0; ng < 4; ng++) {
                    int n = wn * 64 + ng * 16 + (lane & 7) + ((lane >> 4) << 3);
                    int k16 = ks * 2 + ((lane >> 3) & 1);
                    ldm4(bfr[ng], Bb + SWZ(n * 128 + k16 * 16));
                }
#pragma unroll
                for (int mi = 0; mi < 4; mi++)
#pragma unroll
                    for (int ng = 0; ng < 4; ng++) {
                        mma_h(acc[mi][ng * 2 + 0], afr[mi], bfr[ng][0], bfr[ng][1]);
                        mma_h(acc[mi][ng * 2 + 1], afr[mi], bfr[ng][2], bfr[ng][3]);
                    }
            }
        } else {
#pragma unroll
            for (int kc = 0; kc < 2; kc++) {
#pragma unroll
                for (int term = 0; term < 2; term++) {
                    uint32_t Abase = Ab + term * 8192;           // W8a / W8b
                    uint32_t Bbase = Ab + 16384 + term * 8192;   // X8b / X8a
                    uint32_t afr[4][4];
#pragma unroll
                    for (int mi = 0; mi < 4; mi++) {
                        int row = wm * 64 + mi * 16 + (lane & 15);
                        int sg = kc * 2 + (lane >> 4);
                        ldm4(afr[mi], Abase + SWZ(PHYS8(row, sg)));
                    }
                    uint32_t bfr[4][4];
#pragma unroll
                    for (int ng = 0; ng < 4; ng++) {
                        int n = wn * 64 + ng * 16 + (lane & 7) + ((lane >> 4) << 3);
                        int sg = kc * 2 + ((lane >> 3) & 1);
                        ldm4(bfr[ng], Bbase + SWZ(PHYS8(n, sg)));
                    }
#pragma unroll
                    for (int mi = 0; mi < 4; mi++)
#pragma unroll
                        for (int ng = 0; ng < 4; ng++) {
                            mma_q(acc[mi][ng * 2 + 0], afr[mi], bfr[ng][0], bfr[ng][1]);
                            mma_q(acc[mi][ng * 2 + 1], afr[mi], bfr[ng][2], bfr[ng][3]);
                        }
                }
            }
        }
    }

    // epilogue: D * 2^-16 -> out[co*HW + px]
    const float es = 1.f / 65536.f;
#pragma unroll
    for (int mi = 0; mi < 4; mi++) {
        int row0 = coB + wm * 64 + mi * 16 + (lane >> 2);
#pragma unroll
        for (int nj = 0; nj < 8; nj++) {
            int col = pB + wn * 64 + nj * 8 + (lane & 3) * 2;
            float2 v0 = make_float2(acc[mi][nj][0] * es, acc[mi][nj][1] * es);
            float2 v1 = make_float2(acc[mi][nj][2] * es, acc[mi][nj][3] * es);
            *reinterpret_cast<float2*>(out + (size_t)row0 * HW + col) = v0;
            *reinterpret_cast<float2*>(out + (size_t)(row0 + 8) * HW + col) = v1;
        }
    }
}

__global__ __launch_bounds__(128)
void conv_mma_kernel(const __half* __restrict__ x16,
                     const uint8_t* __restrict__ x8a,
                     const uint8_t* __restrict__ x8b, int part,
                     float* __restrict__ out, int flag_n) {
    if (flag_n >= 0 && g_childcount[flag_n] == 0) return;
    extern __shared__ char smem[];
    conv_mma_body(x16, x8a, x8b, part, out, smem);
}

__global__ __launch_bounds__(128)
void conv_mma_dual_kernel(const __half* __restrict__ x160,
                          const uint8_t* __restrict__ x8a0,
                          const uint8_t* __restrict__ x8b0, int part0,
                          float* __restrict__ out0,
                          const __half* __restrict__ x161,
                          const uint8_t* __restrict__ x8a1,
                          const uint8_t* __restrict__ x8b1, int part1,
                          float* __restrict__ out1, int flag_n) {
    if (flag_n >= 0 && g_childcount[flag_n] == 0) return;
    extern __shared__ char smem[];
    if (blockIdx.z == 0) conv_mma_body(x160, x8a0, x8b0, part0, out0, smem);
    else                 conv_mma_body(x161, x8a1, x8b1, part1, out1, smem);
}

// ---------------------------------------------------------------------------
// gather: cs = sum h[k]; rh = sum sigmoid(Gr + cr_n + reset_b + R[k]) * h[k]
// ---------------------------------------------------------------------------
__global__ void gather_kernel(int n, const float* __restrict__ reset_b) {
    int cnt = g_childcount[n];
    if (cnt == 0) return;
    int e = blockIdx.x * 256 + threadIdx.x;
    int c = e >> 12;
    int p = e & (HW - 1);
    int y = p >> 6, x = p & 63;
    const float* t = g_t + (0 * NND + n) * 9 * CHN;
    int ky0 = (y == 0), ky1 = 2 - (y == HH - 1);
    int kx0 = (x == 0), kx1 = 2 - (x == WW - 1);
    float cr = 0.f;
    for (int ky = ky0; ky <= ky1; ky++)
        for (int kx = kx0; kx <= kx1; kx++)
            cr += t[(ky * 3 + kx) * CHN + c];
    float base = g_buf[1 * CHW + e] + reset_b[c] + cr;
    float cs = 0.f, rh = 0.f;
    for (int j = 0; j < cnt; j++) {
        int k = g_child[n * NND + j];
        float hv = g_buf[(8 + k) * CHW + e];
        float rr = sigm(base + g_buf[(28 + k) * CHW + e]);
        cs += hv;
        rh += rr * hv;
    }
    g_buf[4 * CHW + e] = cs;
    g_buf[5 * CHW + e] = rh;
}

// ---------------------------------------------------------------------------
// combine math (per element), shared by the two combine kernels
// ---------------------------------------------------------------------------
__device__ __forceinline__ float combine_elem(int n, int c, int p, bool haskids,
                                              const float* __restrict__ ub,
                                              const float* __restrict__ ob) {
    int e = c * HW + p;
    int y = p >> 6, x = p & 63;
    const float* tu = g_t + (1 * NND + n) * 9 * CHN;
    const float* to = g_t + (2 * NND + n) * 9 * CHN;
    int ky0 = (y == 0), ky1 = 2 - (y == HH - 1);
    int kx0 = (x == 0), kx1 = 2 - (x == WW - 1);
    float cu = 0.f, co = 0.f;
    for (int ky = ky0; ky <= ky1; ky++)
        for (int kx = kx0; kx <= kx1; kx++) {
            int oidx = (ky * 3 + kx) * CHN + c;
            cu += tu[oidx];
            co += to[oidx];
        }
    float uacc = haskids ? g_buf[6 * CHW + e] : 0.f;
    float oacc = haskids ? g_buf[7 * CHW + e] : 0.f;
    float cs   = haskids ? g_buf[4 * CHW + e] : 0.f;
    float z  = sigm(g_buf[2 * CHW + e] + ub[c] + cu + uacc);
    float ri = tanhf(g_buf[3 * CHW + e] + ob[c] + co + oacc);
    return (1.f - z) * ri + z * cs;
}

// root: plain combine -> out
__global__ void combine_kernel(int n, const float* __restrict__ ub,
                               const float* __restrict__ ob,
                               float* __restrict__ dst) {
    int e = blockIdx.x * 256 + threadIdx.x;
    int c = e >> 12, p = e & (HW - 1);
    dst[e] = combine_elem(n, c, p, g_childcount[n] > 0, ub, ob);
}

// non-root: combine + write h plane + emit transposed splits (fused)
__global__ void combine_split_kernel(int n, const float* __restrict__ ub,
                                     const float* __restrict__ ob,
                                     __half* x16, uint8_t* x8a, uint8_t* x8b) {
    __shared__ float tile[32][33];
    int tx = threadIdx.x & 31, ty = threadIdx.x >> 5;
    int p0 = blockIdx.x << 5, c0 = blockIdx.y << 5;
    bool haskids = g_childcount[n] > 0;
    float* hplane = g_buf + (size_t)(8 + n) * CHW;
#pragma unroll
    for (int r = 0; r < 4; r++) {
        int c = c0 + ty + 8 * r, p = p0 + tx;
        float h = combine_elem(n, c, p, haskids, ub, ob);
        hplane[c * HW + p] = h;
        tile[ty + 8 * r][tx] = h;
    }
    __syncthreads();
#pragma unroll
    for (int r = 0; r < 4; r++) {
        int p = p0 + ty + r * 8, ci = c0 + tx;
        split_emit(tile[tx][ty + r * 8], (size_t)p * 512 + ci, x16, x8a, x8b);
    }
}

// ---------------------------------------------------------------------------
extern "C" void kernel_launch(void* const* d_in, const int* in_sizes, int n_in,
                              void* d_out, int out_size) {
    const float* vis  = (const float*)d_in[0];
    const float* lang = (const float*)d_in[1];
    const int*   adj  = (const int*)d_in[2];
    const float* mw   = (const float*)d_in[3];
    const float* mb   = (const float*)d_in[4];
    const float* rw   = (const float*)d_in[5];
    const float* rb   = (const float*)d_in[6];
    const float* uw   = (const float*)d_in[7];
    const float* ub   = (const float*)d_in[8];
    const float* ow   = (const float*)d_in[9];
    const float* ob   = (const float*)d_in[10];
    float* out = (float*)d_out;

    float* buf = nullptr;
    cudaGetSymbolAddress((void**)&buf, g_buf);
    __half* x16 = nullptr;
    uint8_t *x8a = nullptr, *x8b = nullptr;
    cudaGetSymbolAddress((void**)&x16, g_x16);
    cudaGetSymbolAddress((void**)&x8a, g_x8a);
    cudaGetSymbolAddress((void**)&x8b, g_x8b);
    // tensor slots: A = +0, B = +CHW, C = +2*CHW
    __half*  xA16 = x16;            uint8_t *xA8a = x8a,            *xA8b = x8b;
    __half*  xB16 = x16 + CHW;      uint8_t *xB8a = x8a + CHW,      *xB8b = x8b + CHW;
    __half*  xC16 = x16 + 2 * CHW;  uint8_t *xC8a = x8a + 2 * CHW,  *xC8b = x8b + 2 * CHW;

    static bool attr_done = false;
    if (!attr_done) {
        cudaFuncSetAttribute(conv_mma_kernel,
                             cudaFuncAttributeMaxDynamicSharedMemorySize, CONV_SMEM);
        cudaFuncSetAttribute(conv_mma_dual_kernel,
                             cudaFuncAttributeMaxDynamicSharedMemorySize, CONV_SMEM);
        attr_done = true;
    }

    dim3 ggrid(32, 8);            // gemm
    dim3 mgrid(32, 4);            // conv: 32 row-pairs x 4 co-blocks
    dim3 mgrid2(32, 4, 2);        // dual conv
    dim3 sgrid(128, 16);          // split_t / combine_split
    dim3 sgrid2(128, 16, 2);      // dual split_t

    prep_kernel<<<1, 32>>>(adj);
    langbias_kernel<<<40, 256>>>(lang, mw, mb);
    tapconst_kernel<<<54, 256>>>(rw, uw, ow);
    wprep_kernel<<<(6 * 9 * 512 * 512 + 255) / 256, 256>>>(rw, uw, ow);

    // V = conv1x1(vis, mconv_w[:, :512])  (bias folded into b_n)
    gemm_kernel<<<ggrid, 128>>>(vis, mw, 812, 512, buf);

    // shared convs of V (x-part weights of the 3 gates)
    split_t_kernel<<<sgrid, 256>>>(buf, xA16, xA8a, xA8b, -1);
    conv_mma_kernel<<<mgrid, 128, CONV_SMEM>>>(xA16, xA8a, xA8b, 0,
                                               buf + 1 * CHW, -1);        // Gr
    conv_mma_dual_kernel<<<mgrid2, 128, CONV_SMEM>>>(
        xA16, xA8a, xA8b, 2, buf + 2 * CHW,
        xA16, xA8a, xA8b, 4, buf + 3 * CHW, -1);                          // Gu, Go

    // nodes in decreasing index = valid topological order (parent(i) < i)
    for (int n = NND - 1; n >= 0; n--) {
        gather_kernel<<<8192, 256>>>(n, rb);
        split_t_dual_kernel<<<sgrid2, 256>>>(buf + 4 * CHW, xA16, xA8a, xA8b,
                                             buf + 5 * CHW, xB16, xB8a, xB8b,
                                             n);                          // cs, rh
        conv_mma_dual_kernel<<<mgrid2, 128, CONV_SMEM>>>(
            xA16, xA8a, xA8b, 3, buf + 6 * CHW,
            xB16, xB8a, xB8b, 5, buf + 7 * CHW, n);                       // U, O
        if (n == 0) {
            combine_kernel<<<8192, 256>>>(0, ub, ob, out);
        } else {
            combine_split_kernel<<<sgrid, 256>>>(n, ub, ob, xC16, xC8a, xC8b);
            conv_mma_kernel<<<mgrid, 128, CONV_SMEM>>>(xC16, xC8a, xC8b, 1,
                                                       buf + (28 + n) * CHW, -1);
        }
    }
}

// round 10
// speedup vs baseline: 2.2570x; 2.2570x over previous
#include <cuda_runtime.h>
#include <cuda_bf16.h>
#include <cstdio>
#include <cstdint>

#define NND 20
#define CHN 512
#define HH  64
#define WW  64
#define HW  4096
#define CHW 2097152   // 512*64*64
#define NT  1024      // winograd tiles per plane (32x32)

// Big scratch: [V:1][Gr,Gu,Go:3][cs:1][rh:1][U:1][O:1][h:20][R:20] = 48 planes
__device__ float g_buf[48ll * CHW];
__device__ float g_b[NND * CHN];            // per-node channel bias
__device__ float g_t[3 * NND * 9 * CHN];    // per-gate per-node per-tap const vectors
__device__ int   g_childcount[NND];
__device__ int   g_child[NND * NND];

// Winograd-transformed weights: [part(6)][split(2)][j(16)][o(512)][ci(512)] bf16
// parts: 0=reset_x 1=reset_h 2=update_x 3=update_h 4=output_x 5=output_h
__device__ __nv_bfloat16 g_uw[6ll * 2 * 16 * 512 * 512];
// Winograd-transformed inputs: 3 tensors, each [split(2)][j(16)][ci(512)][tile(1024)]
__device__ __nv_bfloat16 g_wV[3ll * 2 * 16 * 512 * NT];
#define VT_STRIDE (2ll * 16 * 512 * NT)
// GEMM outputs: [conv(3)][j(16)][co(512)][tile(1024)] fp32
__device__ float g_m[3ll * 16 * 512 * NT];
#define M_STRIDE (16ll * 512 * NT)

__device__ __forceinline__ float sigm(float v) { return 1.f / (1.f + expf(-v)); }

// ======================= low-level helpers (sm_100-safe) ====================
__device__ __forceinline__ uint32_t smem_u32(const void* p) {
    uint32_t a;
    asm("{ .reg .u64 t; cvta.to.shared.u64 t, %1; cvt.u32.u64 %0, t; }"
        : "=r"(a) : "l"(p));
    return a;
}
__device__ __forceinline__ void cp16(uint32_t dst, const void* src) {
    asm volatile("cp.async.cg.shared.global [%0], [%1], 16;"
        :: "r"(dst), "l"(src) : "memory");
}
__device__ __forceinline__ void ldm4(uint32_t* r, uint32_t addr) {
    asm volatile("ldmatrix.sync.aligned.m8n8.x4.shared.b16 {%0,%1,%2,%3}, [%4];"
        : "=r"(r[0]), "=r"(r[1]), "=r"(r[2]), "=r"(r[3]) : "r"(addr));
}
__device__ __forceinline__ void ldm4t(uint32_t* r, uint32_t addr) {
    asm volatile("ldmatrix.sync.aligned.m8n8.x4.trans.shared.b16 {%0,%1,%2,%3}, [%4];"
        : "=r"(r[0]), "=r"(r[1]), "=r"(r[2]), "=r"(r[3]) : "r"(addr));
}
__device__ __forceinline__ void mma_bf(float* c, const uint32_t* a,
                                       uint32_t b0, uint32_t b1) {
    asm volatile(
        "mma.sync.aligned.m16n8k16.row.col.f32.bf16.bf16.f32 "
        "{%0,%1,%2,%3}, {%4,%5,%6,%7}, {%8,%9}, {%0,%1,%2,%3};"
        : "+f"(c[0]), "+f"(c[1]), "+f"(c[2]), "+f"(c[3])
        : "r"(a[0]), "r"(a[1]), "r"(a[2]), "r"(a[3]), "r"(b0), "r"(b1));
}
#define SWZ(off) ((off) ^ (((off) >> 3) & 0x70))

// ---------------------------------------------------------------------------
// Tree prep
// ---------------------------------------------------------------------------
__global__ void prep_kernel(const int* __restrict__ adj) {
    int n = threadIdx.x;
    if (n < NND) {
        int cnt = 0;
        for (int k = 0; k < NND; k++)
            if (adj[n * NND + k] != 0) g_child[n * NND + cnt++] = k;
        g_childcount[n] = cnt;
    }
}

// ---------------------------------------------------------------------------
// b[n][o] = mconv_b[o] + sum_i mconv_w[o, 512+i] * lang[n, i]
// ---------------------------------------------------------------------------
__global__ void langbias_kernel(const float* __restrict__ lang,
                                const float* __restrict__ mw,
                                const float* __restrict__ mb) {
    int idx = blockIdx.x * 256 + threadIdx.x;
    if (idx >= NND * CHN) return;
    int n = idx / CHN, o = idx - n * CHN;
    const float* wp = mw + o * 812 + 512;
    const float* lp = lang + n * 300;
    float acc = mb[o];
    for (int i = 0; i < 300; i++) acc += wp[i] * lp[i];
    g_b[idx] = acc;
}

// ---------------------------------------------------------------------------
// t[g][n][tap][o] = sum_{i<512} Wg_x[o,i,tap] * b[n][i]
// ---------------------------------------------------------------------------
__global__ void tapconst_kernel(const float* __restrict__ rw,
                                const float* __restrict__ uw,
                                const float* __restrict__ ow) {
    __shared__ float bs[NND * CHN];  // 40KB
    int tid = threadIdx.x;
    for (int idx = tid; idx < NND * CHN; idx += 256) bs[idx] = g_b[idx];
    __syncthreads();
    int gidx = blockIdx.x * 256 + tid;
    int o   = gidx & (CHN - 1);
    int tap = (gidx >> 9) % 9;
    int g   = gidx / (CHN * 9);
    const float* w = (g == 0) ? rw : (g == 1) ? uw : ow;
    const float* wp = w + o * 9216 + tap;
    float acc[NND];
#pragma unroll
    for (int n = 0; n < NND; n++) acc[n] = 0.f;
    for (int i = 0; i < CHN; i++) {
        float wv = wp[i * 9];
#pragma unroll
        for (int n = 0; n < NND; n++) acc[n] += wv * bs[n * CHN + i];
    }
#pragma unroll
    for (int n = 0; n < NND; n++)
        g_t[((g * NND + n) * 9 + tap) * CHN + o] = acc[n];
}

// ---------------------------------------------------------------------------
// Winograd weight transform: U = G g G^T, split hi/lo bf16.
// g_uw[part][split][j][o][ci]
// ---------------------------------------------------------------------------
__global__ void wg_wprep_kernel(const float* __restrict__ rw,
                                const float* __restrict__ uw,
                                const float* __restrict__ ow) {
    int idx = blockIdx.x * 256 + threadIdx.x;
    if (idx >= 6 * 512 * 512) return;
    int ci = idx & 511;
    int o  = (idx >> 9) & 511;
    int part = idx >> 18;
    const float* w = (part < 2) ? rw : (part < 4) ? uw : ow;
    int coff = (part & 1) << 9;
    const float* gp = w + (size_t)o * 9216 + (size_t)(coff + ci) * 9;
    float g[9];
#pragma unroll
    for (int k = 0; k < 9; k++) g[k] = gp[k];
    float a[4][3];
#pragma unroll
    for (int j = 0; j < 3; j++) {
        a[0][j] = g[j];
        a[1][j] = (g[j] + g[3 + j] + g[6 + j]) * 0.5f;
        a[2][j] = (g[j] - g[3 + j] + g[6 + j]) * 0.5f;
        a[3][j] = g[6 + j];
    }
#pragma unroll
    for (int i = 0; i < 4; i++) {
        float U[4];
        U[0] = a[i][0];
        U[1] = (a[i][0] + a[i][1] + a[i][2]) * 0.5f;
        U[2] = (a[i][0] - a[i][1] + a[i][2]) * 0.5f;
        U[3] = a[i][2];
#pragma unroll
        for (int j = 0; j < 4; j++) {
            int j16 = i * 4 + j;
            size_t base = ((((size_t)(part * 2) * 16 + j16) * 512 + o) << 9) + ci;
            __nv_bfloat16 h = __float2bfloat16(U[j]);
            g_uw[base] = h;
            g_uw[base + (size_t)16 * 512 * 512] =
                __float2bfloat16(U[j] - __bfloat162float(h));
        }
    }
}

// ---------------------------------------------------------------------------
// Winograd input transform: src[ci][64][64] fp32 -> V[split][j][ci][tile] bf16
// one block per ci (512 blocks, 256 threads)
// ---------------------------------------------------------------------------
__device__ __forceinline__ void wg_itrans_body(const float* __restrict__ src,
                                               __nv_bfloat16* __restrict__ V,
                                               int ci) {
    __shared__ float psm[66][67];
    int tid = threadIdx.x;
    const float* sp = src + (size_t)ci * HW;
    for (int i = tid; i < 66 * 67; i += 256) (&psm[0][0])[i] = 0.f;
    __syncthreads();
    for (int i = tid; i < 4096; i += 256)
        psm[(i >> 6) + 1][(i & 63) + 1] = sp[i];
    __syncthreads();
    for (int t = tid; t < NT; t += 256) {
        int ty = t >> 5, tx = t & 31;
        float d[4][4];
#pragma unroll
        for (int i = 0; i < 4; i++)
#pragma unroll
            for (int j = 0; j < 4; j++)
                d[i][j] = psm[2 * ty + i][2 * tx + j];
        float tr[4][4];
#pragma unroll
        for (int j = 0; j < 4; j++) {
            tr[0][j] = d[0][j] - d[2][j];
            tr[1][j] = d[1][j] + d[2][j];
            tr[2][j] = d[2][j] - d[1][j];
            tr[3][j] = d[1][j] - d[3][j];
        }
#pragma unroll
        for (int i = 0; i < 4; i++) {
            float v0 = tr[i][0] - tr[i][2];
            float v1 = tr[i][1] + tr[i][2];
            float v2 = tr[i][2] - tr[i][1];
            float v3 = tr[i][1] - tr[i][3];
            float vv[4] = {v0, v1, v2, v3};
#pragma unroll
            for (int j = 0; j < 4; j++) {
                int j16 = i * 4 + j;
                size_t o = ((size_t)j16 * 512 + ci) * NT + t;
                __nv_bfloat16 h = __float2bfloat16(vv[j]);
                V[o] = h;
                V[o + (size_t)16 * 512 * NT] =
                    __float2bfloat16(vv[j] - __bfloat162float(h));
            }
        }
    }
}
__global__ void wg_itrans_kernel(const float* __restrict__ src,
                                 __nv_bfloat16* __restrict__ V, int flag_n) {
    if (flag_n >= 0 && g_childcount[flag_n] == 0) return;
    wg_itrans_body(src, V, blockIdx.x);
}
__global__ void wg_itrans_dual_kernel(const float* __restrict__ s0,
                                      __nv_bfloat16* __restrict__ V0,
                                      const float* __restrict__ s1,
                                      __nv_bfloat16* __restrict__ V1,
                                      int flag_n) {
    if (flag_n >= 0 && g_childcount[flag_n] == 0) return;
    if (blockIdx.z == 0) wg_itrans_body(s0, V0, blockIdx.x);
    else                 wg_itrans_body(s1, V1, blockIdx.x);
}

// ---------------------------------------------------------------------------
// GEMM: V = vis @ W_vis  (1x1 conv), fp32
// ---------------------------------------------------------------------------
__global__ __launch_bounds__(128) void gemm_kernel(
    const float* __restrict__ in, const float* __restrict__ w,
    int ldw, int K, float* __restrict__ out) {
    __shared__ float xs[8 * 128];
    __shared__ float wsm[8 * 65];
    int pB  = blockIdx.x * 128;
    int coB = blockIdx.y * 64;
    int tid = threadIdx.x;
    int pxg = tid & 15, cog = tid >> 4;
    float acc[8][8];
#pragma unroll
    for (int a = 0; a < 8; a++)
#pragma unroll
        for (int b = 0; b < 8; b++) acc[a][b] = 0.f;
    for (int kb = 0; kb < K; kb += 8) {
        __syncthreads();
        for (int idx = tid; idx < 1024; idx += 128) {
            int i = idx >> 7, p = idx & 127;
            xs[idx] = in[(kb + i) * HW + pB + p];
        }
        for (int idx = tid; idx < 512; idx += 128) {
            int co = idx >> 3, i = idx & 7;
            wsm[i * 65 + co] = w[(coB + co) * ldw + kb + i];
        }
        __syncthreads();
#pragma unroll
        for (int i = 0; i < 8; i++) {
            float xv[8], wv[8];
#pragma unroll
            for (int v = 0; v < 8; v++) xv[v] = xs[i * 128 + pxg + 16 * v];
#pragma unroll
            for (int u = 0; u < 8; u++) wv[u] = wsm[i * 65 + u * 8 + cog];
#pragma unroll
            for (int u = 0; u < 8; u++)
#pragma unroll
                for (int v = 0; v < 8; v++)
                    acc[u][v] = fmaf(wv[u], xv[v], acc[u][v]);
        }
    }
#pragma unroll
    for (int u = 0; u < 8; u++) {
        float* op = out + (coB + u * 8 + cog) * HW + pB + pxg;
#pragma unroll
        for (int v = 0; v < 8; v++) op[16 * v] = acc[u][v];
    }
}

// ---------------------------------------------------------------------------
// Winograd GEMM: per j, M_j[co][tile] = U_j[co][ci] * V_j[ci][tile]
// bf16 3-split (hi*hi, lo*hi, hi*lo), fp32 accum. K=512 -> 24 stages of 64.
// CTA 128co x 128tile, 4 warps (2m x 2n), warp tile 64x64.
// grid (8 tileblk, 4 coblk, 16*nconv). 3-slot cp.async pipeline.
// ---------------------------------------------------------------------------
#define WG_SMEM 98304   // 3 x (A 16KB + B 16KB)

__device__ __forceinline__ void wg_issue_stage(
    int s, uint32_t sA, int tid, int tileB, int coB, int part, int j,
    const __nv_bfloat16* V) {
    int s3 = s >> 3;                 // 0,1,2 split term
    int cb = (s & 7) << 6;
    int wsplit = (s3 == 1) ? 1 : 0;
    int xsplit = (s3 == 2) ? 1 : 0;
    const __nv_bfloat16* Abase =
        g_uw + ((((size_t)(part * 2 + wsplit) * 16 + j) * 512 + coB) << 9) + cb;
    const __nv_bfloat16* Bbase =
        V + (((size_t)(xsplit * 16 + j) * 512 + cb) * NT) + tileB;
    uint32_t slot = sA + (s % 3) * 32768;
    // A: 128 co rows x 64 ci, rows 128B, SWZ
#pragma unroll
    for (int it = 0; it < 8; it++) {
        int i = tid + it * 128;
        int o = i >> 3, q = i & 7;
        cp16(slot + SWZ(o * 128 + q * 16), Abase + ((size_t)o << 9) + q * 8);
    }
    // B: 64 ci rows x 128 tiles, rows 256B, chunk-XOR swizzle
#pragma unroll
    for (int it = 0; it < 8; it++) {
        int i = tid + it * 128;
        int k = i >> 4, cc = i & 15;
        cp16(slot + 16384 + k * 256 + ((cc ^ (k & 7)) << 4),
             Bbase + (size_t)k * NT + cc * 8);
    }
    asm volatile("cp.async.commit_group;" ::: "memory");
}

__global__ __launch_bounds__(128)
void wg_gemm_kernel(const __nv_bfloat16* __restrict__ V0, int p0,
                    const __nv_bfloat16* __restrict__ V1, int p1,
                    const __nv_bfloat16* __restrict__ V2, int p2,
                    float* __restrict__ Mbase, int flag_n) {
    if (flag_n >= 0 && g_childcount[flag_n] == 0) return;
    extern __shared__ char smem[];
    uint32_t sA = smem_u32(smem);
    int which = blockIdx.z >> 4;
    int j = blockIdx.z & 15;
    const __nv_bfloat16* V = (which == 0) ? V0 : (which == 1) ? V1 : V2;
    int part = (which == 0) ? p0 : (which == 1) ? p1 : p2;
    float* M = Mbase + (size_t)which * M_STRIDE;

    int tid = threadIdx.x;
    int wid = tid >> 5, lane = tid & 31;
    int tileB = blockIdx.x * 128;
    int coB   = blockIdx.y * 128;
    int wm = wid >> 1;           // co + 64*wm
    int wn = wid & 1;            // tile + 64*wn

    float acc[4][8][4];
#pragma unroll
    for (int a = 0; a < 4; a++)
#pragma unroll
        for (int b = 0; b < 8; b++)
#pragma unroll
            for (int c = 0; c < 4; c++) acc[a][b][c] = 0.f;

    wg_issue_stage(0, sA, tid, tileB, coB, part, j, V);
    wg_issue_stage(1, sA, tid, tileB, coB, part, j, V);

    for (int s = 0; s < 24; s++) {
        asm volatile("cp.async.wait_group 1;" ::: "memory");
        __syncthreads();
        if (s + 2 < 24)
            wg_issue_stage(s + 2, sA, tid, tileB, coB, part, j, V);
        uint32_t Ab = sA + (s % 3) * 32768;
        uint32_t Bb = Ab + 16384;
#pragma unroll
        for (int ks = 0; ks < 4; ks++) {
            uint32_t afr[4][4];
#pragma unroll
            for (int mi = 0; mi < 4; mi++) {
                int row = wm * 64 + mi * 16 + (lane & 15);
                int k16 = ks * 2 + (lane >> 4);
                ldm4(afr[mi], Ab + SWZ(row * 128 + k16 * 16));
            }
            uint32_t bfr[4][4];
#pragma unroll
            for (int ng = 0; ng < 4; ng++) {
                int krow = ks * 16 + (lane & 7) + (((lane >> 3) & 1) << 3);
                int cc   = ((wn * 64 + ng * 16) >> 3) + (lane >> 4);
                ldm4t(bfr[ng], Bb + krow * 256 + ((cc ^ (krow & 7)) << 4));
            }
#pragma unroll
            for (int mi = 0; mi < 4; mi++)
#pragma unroll
                for (int ng = 0; ng < 4; ng++) {
                    mma_bf(acc[mi][ng * 2 + 0], afr[mi], bfr[ng][0], bfr[ng][1]);
                    mma_bf(acc[mi][ng * 2 + 1], afr[mi], bfr[ng][2], bfr[ng][3]);
                }
        }
        __syncthreads();
    }

    // epilogue: M[j][co][tile]
#pragma unroll
    for (int mi = 0; mi < 4; mi++) {
        int row0 = coB + wm * 64 + mi * 16 + (lane >> 2);
        float* mp0 = M + ((size_t)j * 512 + row0) * NT + tileB;
#pragma unroll
        for (int nj = 0; nj < 8; nj++) {
            int col = wn * 64 + nj * 8 + (lane & 3) * 2;
            *reinterpret_cast<float2*>(mp0 + col) =
                make_float2(acc[mi][nj][0], acc[mi][nj][1]);
            *reinterpret_cast<float2*>(mp0 + 8 * NT + col) =
                make_float2(acc[mi][nj][2], acc[mi][nj][3]);
        }
    }
}

// ---------------------------------------------------------------------------
// Winograd inverse transform: Y = A^T Z A per (co, tile), Z = M[j][co][tile]
// grid (2048, nconv), 256 threads
// ---------------------------------------------------------------------------
__global__ void wg_inv_kernel(float* __restrict__ D0, float* __restrict__ D1,
                              float* __restrict__ D2, int flag_n) {
    if (flag_n >= 0 && g_childcount[flag_n] == 0) return;
    int conv = blockIdx.y;
    const float* M = g_m + (size_t)conv * M_STRIDE;
    float* D = (conv == 0) ? D0 : (conv == 1) ? D1 : D2;
    int e = blockIdx.x * 256 + threadIdx.x;      // 0..524287
    int co = e >> 10, t = e & (NT - 1);
    float Z[16];
#pragma unroll
    for (int j = 0; j < 16; j++)
        Z[j] = M[((size_t)j * 512 + co) * NT + t];
    float s0[4], s1[4];
#pragma unroll
    for (int j = 0; j < 4; j++) {
        s0[j] = Z[j] + Z[4 + j] + Z[8 + j];
        s1[j] = Z[4 + j] - Z[8 + j] - Z[12 + j];
    }
    float y00 = s0[0] + s0[1] + s0[2];
    float y01 = s0[1] - s0[2] - s0[3];
    float y10 = s1[0] + s1[1] + s1[2];
    float y11 = s1[1] - s1[2] - s1[3];
    int ty = t >> 5, tx = t & 31;
    float* op = D + (size_t)co * HW + (ty * 2) * WW + tx * 2;
    *reinterpret_cast<float2*>(op)      = make_float2(y00, y01);
    *reinterpret_cast<float2*>(op + WW) = make_float2(y10, y11);
}

// ---------------------------------------------------------------------------
// gather: cs = sum h[k]; rh = sum sigmoid(Gr + cr_n + reset_b + R[k]) * h[k]
// ---------------------------------------------------------------------------
__global__ void gather_kernel(int n, const float* __restrict__ reset_b) {
    int cnt = g_childcount[n];
    if (cnt == 0) return;
    int e = blockIdx.x * 256 + threadIdx.x;
    int c = e >> 12;
    int p = e & (HW - 1);
    int y = p >> 6, x = p & 63;
    const float* t = g_t + (0 * NND + n) * 9 * CHN;
    int ky0 = (y == 0), ky1 = 2 - (y == HH - 1);
    int kx0 = (x == 0), kx1 = 2 - (x == WW - 1);
    float cr = 0.f;
    for (int ky = ky0; ky <= ky1; ky++)
        for (int kx = kx0; kx <= kx1; kx++)
            cr += t[(ky * 3 + kx) * CHN + c];
    float base = g_buf[1 * CHW + e] + reset_b[c] + cr;
    float cs = 0.f, rh = 0.f;
    for (int j = 0; j < cnt; j++) {
        int k = g_child[n * NND + j];
        float hv = g_buf[(8 + k) * CHW + e];
        float rr = sigm(base + g_buf[(28 + k) * CHW + e]);
        cs += hv;
        rh += rr * hv;
    }
    g_buf[4 * CHW + e] = cs;
    g_buf[5 * CHW + e] = rh;
}

// ---------------------------------------------------------------------------
// combine: h[n] = (1-z)*tanh(Go + co_n + output_b + O) + z*cs
// ---------------------------------------------------------------------------
__global__ void combine_kernel(int n, const float* __restrict__ ub,
                               const float* __restrict__ ob,
                               float* __restrict__ dst) {
    int e = blockIdx.x * 256 + threadIdx.x;
    int c = e >> 12;
    int p = e & (HW - 1);
    int y = p >> 6, x = p & 63;
    bool haskids = g_childcount[n] > 0;
    const float* tu = g_t + (1 * NND + n) * 9 * CHN;
    const float* to = g_t + (2 * NND + n) * 9 * CHN;
    int ky0 = (y == 0), ky1 = 2 - (y == HH - 1);
    int kx0 = (x == 0), kx1 = 2 - (x == WW - 1);
    float cu = 0.f, co = 0.f;
    for (int ky = ky0; ky <= ky1; ky++)
        for (int kx = kx0; kx <= kx1; kx++) {
            int oidx = (ky * 3 + kx) * CHN + c;
            cu += tu[oidx];
            co += to[oidx];
        }
    float uacc = haskids ? g_buf[6 * CHW + e] : 0.f;
    float oacc = haskids ? g_buf[7 * CHW + e] : 0.f;
    float cs   = haskids ? g_buf[4 * CHW + e] : 0.f;
    float z  = sigm(g_buf[2 * CHW + e] + ub[c] + cu + uacc);
    float ri = tanhf(g_buf[3 * CHW + e] + ob[c] + co + oacc);
    dst[e] = (1.f - z) * ri + z * cs;
}

// ---------------------------------------------------------------------------
extern "C" void kernel_launch(void* const* d_in, const int* in_sizes, int n_in,
                              void* d_out, int out_size) {
    const float* vis  = (const float*)d_in[0];
    const float* lang = (const float*)d_in[1];
    const int*   adj  = (const int*)d_in[2];
    const float* mw   = (const float*)d_in[3];
    const float* mb   = (const float*)d_in[4];
    const float* rw   = (const float*)d_in[5];
    const float* rb   = (const float*)d_in[6];
    const float* uw   = (const float*)d_in[7];
    const float* ub   = (const float*)d_in[8];
    const float* ow   = (const float*)d_in[9];
    const float* ob   = (const float*)d_in[10];
    float* out = (float*)d_out;

    float* buf = nullptr;
    cudaGetSymbolAddress((void**)&buf, g_buf);
    __nv_bfloat16* wv = nullptr;
    cudaGetSymbolAddress((void**)&wv, g_wV);
    float* m = nullptr;
    cudaGetSymbolAddress((void**)&m, g_m);
    __nv_bfloat16* V0 = wv;
    __nv_bfloat16* V1 = wv + VT_STRIDE;
    __nv_bfloat16* V2 = wv + 2 * VT_STRIDE;

    static bool attr_done = false;
    if (!attr_done) {
        cudaFuncSetAttribute(wg_gemm_kernel,
                             cudaFuncAttributeMaxDynamicSharedMemorySize, WG_SMEM);
        attr_done = true;
    }

    dim3 ggrid(32, 8);                 // 1x1 gemm
    dim3 wgrid1(8, 4, 16);             // winograd gemm, 1 conv
    dim3 wgrid2(8, 4, 32);             // 2 convs
    dim3 wgrid3(8, 4, 48);             // 3 convs
    dim3 itg(512), itg2(512, 1, 2);    // input transform
    dim3 inv1(2048, 1), inv2(2048, 2), inv3(2048, 3);

    prep_kernel<<<1, 32>>>(adj);
    langbias_kernel<<<40, 256>>>(lang, mw, mb);
    tapconst_kernel<<<54, 256>>>(rw, uw, ow);
    wg_wprep_kernel<<<6144, 256>>>(rw, uw, ow);

    // V-plane = conv1x1(vis, mconv_w[:, :512])  (bias folded into b_n)
    gemm_kernel<<<ggrid, 128>>>(vis, mw, 812, 512, buf);

    // shared convs of V (x-part weights of the 3 gates): Gr, Gu, Go
    wg_itrans_kernel<<<itg, 256>>>(buf, V0, -1);
    wg_gemm_kernel<<<wgrid3, 128, WG_SMEM>>>(V0, 0, V0, 2, V0, 4, m, -1);
    wg_inv_kernel<<<inv3, 256>>>(buf + 1 * CHW, buf + 2 * CHW, buf + 3 * CHW, -1);

    // nodes in decreasing index = valid topological order (parent(i) < i)
    for (int n = NND - 1; n >= 0; n--) {
        gather_kernel<<<8192, 256>>>(n, rb);
        wg_itrans_dual_kernel<<<itg2, 256>>>(buf + 4 * CHW, V0,
                                             buf + 5 * CHW, V1, n);   // cs, rh
        wg_gemm_kernel<<<wgrid2, 128, WG_SMEM>>>(V0, 3, V1, 5, V1, 5, m, n);
        wg_inv_kernel<<<inv2, 256>>>(buf + 6 * CHW, buf + 7 * CHW,
                                     buf + 7 * CHW, n);               // U, O
        combine_kernel<<<8192, 256>>>(n, ub, ob,
                                      (n == 0) ? out : buf + (8 + n) * CHW);
        if (n > 0) {  // R[n] = conv3x3(h[n], Wr_h)
            wg_itrans_kernel<<<itg, 256>>>(buf + (8 + n) * CHW, V2, -1);
            wg_gemm_kernel<<<wgrid1, 128, WG_SMEM>>>(V2, 1, V2, 1, V2, 1, m, -1);
            wg_inv_kernel<<<inv1, 256>>>(buf + (28 + n) * CHW,
                                         buf + (28 + n) * CHW,
                                         buf + (28 + n) * CHW, -1);
        }
    }
}

// round 11
// speedup vs baseline: 3.2270x; 1.4298x over previous
#include <cuda_runtime.h>
#include <cuda_bf16.h>
#include <cstdio>
#include <cstdint>

#define NND 20
#define CHN 512
#define HH  64
#define WW  64
#define HW  4096
#define CHW 2097152   // 512*64*64
#define NT2 256       // winograd F(4,3) tiles per plane (16x16)
#define NJ  36        // 6x6 transform coefficients

// Big scratch: [V:1][Gr,Gu,Go:3][cs:1][rh:1][U:1][O:1][h:20][R:20] = 48 planes
__device__ float g_buf[48ll * CHW];
__device__ float g_b[NND * CHN];            // per-node channel bias
__device__ float g_t[3 * NND * 9 * CHN];    // per-gate per-node per-tap const vectors
__device__ int   g_childcount[NND];
__device__ int   g_child[NND * NND];

// Winograd-transformed weights: [part(6)][split(2)][j(36)][o(512)][ci(512)] bf16
// parts: 0=reset_x 1=reset_h 2=update_x 3=update_h 4=output_x 5=output_h
__device__ __nv_bfloat16 g_uw[6ll * 2 * NJ * 512 * 512];
// Winograd-transformed inputs: 3 tensors, each [split(2)][j(36)][ci(512)][tile(256)]
__device__ __nv_bfloat16 g_wV[3ll * 2 * NJ * 512 * NT2];
#define VT_STRIDE (2ll * NJ * 512 * NT2)
// GEMM outputs: [conv(3)][j(36)][co(512)][tile(256)] fp32
__device__ float g_m[3ll * NJ * 512 * NT2];
#define M_STRIDE ((size_t)NJ * 512 * NT2)

__device__ __forceinline__ float sigm(float v) { return 1.f / (1.f + expf(-v)); }

// ======================= low-level helpers (sm_100-safe) ====================
__device__ __forceinline__ uint32_t smem_u32(const void* p) {
    uint32_t a;
    asm("{ .reg .u64 t; cvta.to.shared.u64 t, %1; cvt.u32.u64 %0, t; }"
        : "=r"(a) : "l"(p));
    return a;
}
__device__ __forceinline__ void cp16(uint32_t dst, const void* src) {
    asm volatile("cp.async.cg.shared.global [%0], [%1], 16;"
        :: "r"(dst), "l"(src) : "memory");
}
__device__ __forceinline__ void ldm4(uint32_t* r, uint32_t addr) {
    asm volatile("ldmatrix.sync.aligned.m8n8.x4.shared.b16 {%0,%1,%2,%3}, [%4];"
        : "=r"(r[0]), "=r"(r[1]), "=r"(r[2]), "=r"(r[3]) : "r"(addr));
}
__device__ __forceinline__ void ldm4t(uint32_t* r, uint32_t addr) {
    asm volatile("ldmatrix.sync.aligned.m8n8.x4.trans.shared.b16 {%0,%1,%2,%3}, [%4];"
        : "=r"(r[0]), "=r"(r[1]), "=r"(r[2]), "=r"(r[3]) : "r"(addr));
}
__device__ __forceinline__ void mma_bf(float* c, const uint32_t* a,
                                       uint32_t b0, uint32_t b1) {
    asm volatile(
        "mma.sync.aligned.m16n8k16.row.col.f32.bf16.bf16.f32 "
        "{%0,%1,%2,%3}, {%4,%5,%6,%7}, {%8,%9}, {%0,%1,%2,%3};"
        : "+f"(c[0]), "+f"(c[1]), "+f"(c[2]), "+f"(c[3])
        : "r"(a[0]), "r"(a[1]), "r"(a[2]), "r"(a[3]), "r"(b0), "r"(b1));
}
#define SWZ(off) ((off) ^ (((off) >> 3) & 0x70))

// ---------------------------------------------------------------------------
// Tree prep
// ---------------------------------------------------------------------------
__global__ void prep_kernel(const int* __restrict__ adj) {
    int n = threadIdx.x;
    if (n < NND) {
        int cnt = 0;
        for (int k = 0; k < NND; k++)
            if (adj[n * NND + k] != 0) g_child[n * NND + cnt++] = k;
        g_childcount[n] = cnt;
    }
}

// ---------------------------------------------------------------------------
// b[n][o] = mconv_b[o] + sum_i mconv_w[o, 512+i] * lang[n, i]
// ---------------------------------------------------------------------------
__global__ void langbias_kernel(const float* __restrict__ lang,
                                const float* __restrict__ mw,
                                const float* __restrict__ mb) {
    int idx = blockIdx.x * 256 + threadIdx.x;
    if (idx >= NND * CHN) return;
    int n = idx / CHN, o = idx - n * CHN;
    const float* wp = mw + o * 812 + 512;
    const float* lp = lang + n * 300;
    float acc = mb[o];
    for (int i = 0; i < 300; i++) acc += wp[i] * lp[i];
    g_b[idx] = acc;
}

// ---------------------------------------------------------------------------
// t[g][n][tap][o] = sum_{i<512} Wg_x[o,i,tap] * b[n][i]
// ---------------------------------------------------------------------------
__global__ void tapconst_kernel(const float* __restrict__ rw,
                                const float* __restrict__ uw,
                                const float* __restrict__ ow) {
    __shared__ float bs[NND * CHN];  // 40KB
    int tid = threadIdx.x;
    for (int idx = tid; idx < NND * CHN; idx += 256) bs[idx] = g_b[idx];
    __syncthreads();
    int gidx = blockIdx.x * 256 + tid;
    int o   = gidx & (CHN - 1);
    int tap = (gidx >> 9) % 9;
    int g   = gidx / (CHN * 9);
    const float* w = (g == 0) ? rw : (g == 1) ? uw : ow;
    const float* wp = w + o * 9216 + tap;
    float acc[NND];
#pragma unroll
    for (int n = 0; n < NND; n++) acc[n] = 0.f;
    for (int i = 0; i < CHN; i++) {
        float wv = wp[i * 9];
#pragma unroll
        for (int n = 0; n < NND; n++) acc[n] += wv * bs[n * CHN + i];
    }
#pragma unroll
    for (int n = 0; n < NND; n++)
        g_t[((g * NND + n) * 9 + tap) * CHN + o] = acc[n];
}

// ---------------------------------------------------------------------------
// F(4,3) weight transform: U = G g G^T (6x6), split hi/lo bf16.
// G-transform of 3-vector
// ---------------------------------------------------------------------------
__device__ __forceinline__ void gtrans(float v0, float v1, float v2, float* u) {
    u[0] = 0.25f * v0;
    u[1] = -(v0 + v1 + v2) * (1.f / 6.f);
    u[2] = (-v0 + v1 - v2) * (1.f / 6.f);
    u[3] = (v0 + 2.f * v1 + 4.f * v2) * (1.f / 24.f);
    u[4] = (v0 - 2.f * v1 + 4.f * v2) * (1.f / 24.f);
    u[5] = v2;
}
__global__ void wg_wprep_kernel(const float* __restrict__ rw,
                                const float* __restrict__ uw,
                                const float* __restrict__ ow) {
    int idx = blockIdx.x * 256 + threadIdx.x;
    if (idx >= 6 * 512 * 512) return;
    int ci = idx & 511;
    int o  = (idx >> 9) & 511;
    int part = idx >> 18;
    const float* w = (part < 2) ? rw : (part < 4) ? uw : ow;
    int coff = (part & 1) << 9;
    const float* gp = w + (size_t)o * 9216 + (size_t)(coff + ci) * 9;
    float g[9];
#pragma unroll
    for (int k = 0; k < 9; k++) g[k] = gp[k];
    float a[6][3];
#pragma unroll
    for (int j = 0; j < 3; j++) {
        float u[6];
        gtrans(g[j], g[3 + j], g[6 + j], u);
#pragma unroll
        for (int i = 0; i < 6; i++) a[i][j] = u[i];
    }
#pragma unroll
    for (int i = 0; i < 6; i++) {
        float U[6];
        gtrans(a[i][0], a[i][1], a[i][2], U);
#pragma unroll
        for (int j = 0; j < 6; j++) {
            int j36 = i * 6 + j;
            size_t base = ((((size_t)(part * 2) * NJ + j36) * 512 + o) << 9) + ci;
            __nv_bfloat16 h = __float2bfloat16(U[j]);
            g_uw[base] = h;
            g_uw[base + (size_t)NJ * 512 * 512] =
                __float2bfloat16(U[j] - __bfloat162float(h));
        }
    }
}

// ---------------------------------------------------------------------------
// F(4,3) input transform: src[ci][64][64] fp32 -> V[split][j][ci][tile] bf16
// one block per ci (512 blocks, 256 threads = 1 tile/thread)
// ---------------------------------------------------------------------------
__device__ __forceinline__ void bttrans(const float* v, float* w) {
    w[0] = 4.f * v[0] - 5.f * v[2] + v[4];
    w[1] = -4.f * v[1] - 4.f * v[2] + v[3] + v[4];
    w[2] = 4.f * v[1] - 4.f * v[2] - v[3] + v[4];
    w[3] = -2.f * v[1] - v[2] + 2.f * v[3] + v[4];
    w[4] = 2.f * v[1] - v[2] - 2.f * v[3] + v[4];
    w[5] = 4.f * v[1] - 5.f * v[3] + v[5];
}
__device__ __forceinline__ void wg_itrans_body(const float* __restrict__ src,
                                               __nv_bfloat16* __restrict__ V,
                                               int ci) {
    __shared__ float psm[66][67];
    int tid = threadIdx.x;
    const float* sp = src + (size_t)ci * HW;
    for (int i = tid; i < 66 * 67; i += 256) (&psm[0][0])[i] = 0.f;
    __syncthreads();
    for (int i = tid; i < 4096; i += 256)
        psm[(i >> 6) + 1][(i & 63) + 1] = sp[i];
    __syncthreads();
    int t = tid;                      // 256 tiles
    int ty = t >> 4, tx = t & 15;
    float d[6][6];
#pragma unroll
    for (int i = 0; i < 6; i++)
#pragma unroll
        for (int j = 0; j < 6; j++)
            d[i][j] = psm[4 * ty + i][4 * tx + j];
    float c[6][6];
#pragma unroll
    for (int j = 0; j < 6; j++) {     // columns
        float vin[6], vo[6];
#pragma unroll
        for (int i = 0; i < 6; i++) vin[i] = d[i][j];
        bttrans(vin, vo);
#pragma unroll
        for (int i = 0; i < 6; i++) c[i][j] = vo[i];
    }
#pragma unroll
    for (int i = 0; i < 6; i++) {     // rows
        float vo[6];
        bttrans(c[i], vo);
#pragma unroll
        for (int j = 0; j < 6; j++) {
            int j36 = i * 6 + j;
            size_t o = ((size_t)j36 * 512 + ci) * NT2 + t;
            __nv_bfloat16 h = __float2bfloat16(vo[j]);
            V[o] = h;
            V[o + (size_t)NJ * 512 * NT2] =
                __float2bfloat16(vo[j] - __bfloat162float(h));
        }
    }
}
__global__ void wg_itrans_kernel(const float* __restrict__ src,
                                 __nv_bfloat16* __restrict__ V, int flag_n) {
    if (flag_n >= 0 && g_childcount[flag_n] == 0) return;
    wg_itrans_body(src, V, blockIdx.x);
}
__global__ void wg_itrans_dual_kernel(const float* __restrict__ s0,
                                      __nv_bfloat16* __restrict__ V0,
                                      const float* __restrict__ s1,
                                      __nv_bfloat16* __restrict__ V1,
                                      int flag_n) {
    if (flag_n >= 0 && g_childcount[flag_n] == 0) return;
    if (blockIdx.z == 0) wg_itrans_body(s0, V0, blockIdx.x);
    else                 wg_itrans_body(s1, V1, blockIdx.x);
}

// ---------------------------------------------------------------------------
// GEMM: V = vis @ W_vis  (1x1 conv), fp32
// ---------------------------------------------------------------------------
__global__ __launch_bounds__(128) void gemm_kernel(
    const float* __restrict__ in, const float* __restrict__ w,
    int ldw, int K, float* __restrict__ out) {
    __shared__ float xs[8 * 128];
    __shared__ float wsm[8 * 65];
    int pB  = blockIdx.x * 128;
    int coB = blockIdx.y * 64;
    int tid = threadIdx.x;
    int pxg = tid & 15, cog = tid >> 4;
    float acc[8][8];
#pragma unroll
    for (int a = 0; a < 8; a++)
#pragma unroll
        for (int b = 0; b < 8; b++) acc[a][b] = 0.f;
    for (int kb = 0; kb < K; kb += 8) {
        __syncthreads();
        for (int idx = tid; idx < 1024; idx += 128) {
            int i = idx >> 7, p = idx & 127;
            xs[idx] = in[(kb + i) * HW + pB + p];
        }
        for (int idx = tid; idx < 512; idx += 128) {
            int co = idx >> 3, i = idx & 7;
            wsm[i * 65 + co] = w[(coB + co) * ldw + kb + i];
        }
        __syncthreads();
#pragma unroll
        for (int i = 0; i < 8; i++) {
            float xv[8], wv[8];
#pragma unroll
            for (int v = 0; v < 8; v++) xv[v] = xs[i * 128 + pxg + 16 * v];
#pragma unroll
            for (int u = 0; u < 8; u++) wv[u] = wsm[i * 65 + u * 8 + cog];
#pragma unroll
            for (int u = 0; u < 8; u++)
#pragma unroll
                for (int v = 0; v < 8; v++)
                    acc[u][v] = fmaf(wv[u], xv[v], acc[u][v]);
        }
    }
#pragma unroll
    for (int u = 0; u < 8; u++) {
        float* op = out + (coB + u * 8 + cog) * HW + pB + pxg;
#pragma unroll
        for (int v = 0; v < 8; v++) op[16 * v] = acc[u][v];
    }
}

// ---------------------------------------------------------------------------
// Winograd GEMM: per j, M_j[co][tile] = U_j[co][ci] * V_j[ci][tile]
// bf16 3-split, fp32 accum. K=512 -> 24 stages of 64.
// CTA 128co x 128tile, 4 warps (2m x 2n). grid (2, 4, 36*nconv).
// ---------------------------------------------------------------------------
#define WG_SMEM 98304   // 3 x (A 16KB + B 16KB)

__device__ __forceinline__ void wg_issue_stage(
    int s, uint32_t sA, int tid, int tileB, int coB, int part, int j,
    const __nv_bfloat16* V) {
    int s3 = s >> 3;                 // 0,1,2 split term
    int cb = (s & 7) << 6;
    int wsplit = (s3 == 1) ? 1 : 0;
    int xsplit = (s3 == 2) ? 1 : 0;
    const __nv_bfloat16* Abase =
        g_uw + ((((size_t)(part * 2 + wsplit) * NJ + j) * 512 + coB) << 9) + cb;
    const __nv_bfloat16* Bbase =
        V + (((size_t)(xsplit * NJ + j) * 512 + cb) * NT2) + tileB;
    uint32_t slot = sA + (s % 3) * 32768;
    // A: 128 co rows x 64 ci, rows 128B, SWZ
#pragma unroll
    for (int it = 0; it < 8; it++) {
        int i = tid + it * 128;
        int o = i >> 3, q = i & 7;
        cp16(slot + SWZ(o * 128 + q * 16), Abase + ((size_t)o << 9) + q * 8);
    }
    // B: 64 ci rows x 128 tiles, rows 256B, chunk-XOR swizzle
#pragma unroll
    for (int it = 0; it < 8; it++) {
        int i = tid + it * 128;
        int k = i >> 4, cc = i & 15;
        cp16(slot + 16384 + k * 256 + ((cc ^ (k & 7)) << 4),
             Bbase + (size_t)k * NT2 + cc * 8);
    }
    asm volatile("cp.async.commit_group;" ::: "memory");
}

__global__ __launch_bounds__(128)
void wg_gemm_kernel(const __nv_bfloat16* __restrict__ V0, int p0,
                    const __nv_bfloat16* __restrict__ V1, int p1,
                    const __nv_bfloat16* __restrict__ V2, int p2,
                    float* __restrict__ Mbase, int flag_n) {
    if (flag_n >= 0 && g_childcount[flag_n] == 0) return;
    extern __shared__ char smem[];
    uint32_t sA = smem_u32(smem);
    int which = blockIdx.z / NJ;
    int j = blockIdx.z - which * NJ;
    const __nv_bfloat16* V = (which == 0) ? V0 : (which == 1) ? V1 : V2;
    int part = (which == 0) ? p0 : (which == 1) ? p1 : p2;
    float* M = Mbase + (size_t)which * M_STRIDE;

    int tid = threadIdx.x;
    int wid = tid >> 5, lane = tid & 31;
    int tileB = blockIdx.x * 128;
    int coB   = blockIdx.y * 128;
    int wm = wid >> 1;           // co + 64*wm
    int wn = wid & 1;            // tile + 64*wn

    float acc[4][8][4];
#pragma unroll
    for (int a = 0; a < 4; a++)
#pragma unroll
        for (int b = 0; b < 8; b++)
#pragma unroll
            for (int c = 0; c < 4; c++) acc[a][b][c] = 0.f;

    wg_issue_stage(0, sA, tid, tileB, coB, part, j, V);
    wg_issue_stage(1, sA, tid, tileB, coB, part, j, V);

    for (int s = 0; s < 24; s++) {
        asm volatile("cp.async.wait_group 1;" ::: "memory");
        __syncthreads();
        if (s + 2 < 24)
            wg_issue_stage(s + 2, sA, tid, tileB, coB, part, j, V);
        uint32_t Ab = sA + (s % 3) * 32768;
        uint32_t Bb = Ab + 16384;
#pragma unroll
        for (int ks = 0; ks < 4; ks++) {
            uint32_t afr[4][4];
#pragma unroll
            for (int mi = 0; mi < 4; mi++) {
                int row = wm * 64 + mi * 16 + (lane & 15);
                int k16 = ks * 2 + (lane >> 4);
                ldm4(afr[mi], Ab + SWZ(row * 128 + k16 * 16));
            }
            uint32_t bfr[4][4];
#pragma unroll
            for (int ng = 0; ng < 4; ng++) {
                int krow = ks * 16 + (lane & 7) + (((lane >> 3) & 1) << 3);
                int cc   = ((wn * 64 + ng * 16) >> 3) + (lane >> 4);
                ldm4t(bfr[ng], Bb + krow * 256 + ((cc ^ (krow & 7)) << 4));
            }
#pragma unroll
            for (int mi = 0; mi < 4; mi++)
#pragma unroll
                for (int ng = 0; ng < 4; ng++) {
                    mma_bf(acc[mi][ng * 2 + 0], afr[mi], bfr[ng][0], bfr[ng][1]);
                    mma_bf(acc[mi][ng * 2 + 1], afr[mi], bfr[ng][2], bfr[ng][3]);
                }
        }
        __syncthreads();
    }

    // epilogue: M[j][co][tile]
#pragma unroll
    for (int mi = 0; mi < 4; mi++) {
        int row0 = coB + wm * 64 + mi * 16 + (lane >> 2);
        float* mp0 = M + ((size_t)j * 512 + row0) * NT2 + tileB;
#pragma unroll
        for (int nj = 0; nj < 8; nj++) {
            int col = wn * 64 + nj * 8 + (lane & 3) * 2;
            *reinterpret_cast<float2*>(mp0 + col) =
                make_float2(acc[mi][nj][0], acc[mi][nj][1]);
            *reinterpret_cast<float2*>(mp0 + 8 * NT2 + col) =
                make_float2(acc[mi][nj][2], acc[mi][nj][3]);
        }
    }
}

// ---------------------------------------------------------------------------
// F(4,3) inverse transform: Y = A^T Z A per (co, tile)
// grid (512, nconv), 256 threads; e over 512co x 256t
// ---------------------------------------------------------------------------
__device__ __forceinline__ void attrans(const float* v, float* y) {
    y[0] = v[0] + v[1] + v[2] + v[3] + v[4];
    y[1] = v[1] - v[2] + 2.f * (v[3] - v[4]);
    y[2] = v[1] + v[2] + 4.f * (v[3] + v[4]);
    y[3] = v[1] - v[2] + 8.f * (v[3] - v[4]) + v[5];
}
__global__ void wg_inv_kernel(float* __restrict__ D0, float* __restrict__ D1,
                              float* __restrict__ D2, int flag_n) {
    if (flag_n >= 0 && g_childcount[flag_n] == 0) return;
    int conv = blockIdx.y;
    const float* M = g_m + (size_t)conv * M_STRIDE;
    float* D = (conv == 0) ? D0 : (conv == 1) ? D1 : D2;
    int e = blockIdx.x * 256 + threadIdx.x;      // 0..131071
    int co = e >> 8, t = e & (NT2 - 1);
    float Z[6][6];
#pragma unroll
    for (int i = 0; i < 6; i++)
#pragma unroll
        for (int j = 0; j < 6; j++)
            Z[i][j] = M[((size_t)(i * 6 + j) * 512 + co) * NT2 + t];
    float c[4][6];
#pragma unroll
    for (int j = 0; j < 6; j++) {     // columns
        float vin[6], vo[4];
#pragma unroll
        for (int i = 0; i < 6; i++) vin[i] = Z[i][j];
        attrans(vin, vo);
#pragma unroll
        for (int i = 0; i < 4; i++) c[i][j] = vo[i];
    }
    int ty = t >> 4, tx = t & 15;
    float* op = D + (size_t)co * HW + (4 * ty) * WW + 4 * tx;
#pragma unroll
    for (int i = 0; i < 4; i++) {     // rows
        float y[4];
        attrans(c[i], y);
        *reinterpret_cast<float4*>(op + i * WW) =
            make_float4(y[0], y[1], y[2], y[3]);
    }
}

// ---------------------------------------------------------------------------
// gather: cs = sum h[k]; rh = sum sigmoid(Gr + cr_n + reset_b + R[k]) * h[k]
// ---------------------------------------------------------------------------
__global__ void gather_kernel(int n, const float* __restrict__ reset_b) {
    int cnt = g_childcount[n];
    if (cnt == 0) return;
    int e = blockIdx.x * 256 + threadIdx.x;
    int c = e >> 12;
    int p = e & (HW - 1);
    int y = p >> 6, x = p & 63;
    const float* t = g_t + (0 * NND + n) * 9 * CHN;
    int ky0 = (y == 0), ky1 = 2 - (y == HH - 1);
    int kx0 = (x == 0), kx1 = 2 - (x == WW - 1);
    float cr = 0.f;
    for (int ky = ky0; ky <= ky1; ky++)
        for (int kx = kx0; kx <= kx1; kx++)
            cr += t[(ky * 3 + kx) * CHN + c];
    float base = g_buf[1 * CHW + e] + reset_b[c] + cr;
    float cs = 0.f, rh = 0.f;
    for (int j = 0; j < cnt; j++) {
        int k = g_child[n * NND + j];
        float hv = g_buf[(8 + k) * CHW + e];
        float rr = sigm(base + g_buf[(28 + k) * CHW + e]);
        cs += hv;
        rh += rr * hv;
    }
    g_buf[4 * CHW + e] = cs;
    g_buf[5 * CHW + e] = rh;
}

// ---------------------------------------------------------------------------
// combine: h[n] = (1-z)*tanh(Go + co_n + output_b + O) + z*cs
// ---------------------------------------------------------------------------
__global__ void combine_kernel(int n, const float* __restrict__ ub,
                               const float* __restrict__ ob,
                               float* __restrict__ dst) {
    int e = blockIdx.x * 256 + threadIdx.x;
    int c = e >> 12;
    int p = e & (HW - 1);
    int y = p >> 6, x = p & 63;
    bool haskids = g_childcount[n] > 0;
    const float* tu = g_t + (1 * NND + n) * 9 * CHN;
    const float* to = g_t + (2 * NND + n) * 9 * CHN;
    int ky0 = (y == 0), ky1 = 2 - (y == HH - 1);
    int kx0 = (x == 0), kx1 = 2 - (x == WW - 1);
    float cu = 0.f, co = 0.f;
    for (int ky = ky0; ky <= ky1; ky++)
        for (int kx = kx0; kx <= kx1; kx++) {
            int oidx = (ky * 3 + kx) * CHN + c;
            cu += tu[oidx];
            co += to[oidx];
        }
    float uacc = haskids ? g_buf[6 * CHW + e] : 0.f;
    float oacc = haskids ? g_buf[7 * CHW + e] : 0.f;
    float cs   = haskids ? g_buf[4 * CHW + e] : 0.f;
    float z  = sigm(g_buf[2 * CHW + e] + ub[c] + cu + uacc);
    float ri = tanhf(g_buf[3 * CHW + e] + ob[c] + co + oacc);
    dst[e] = (1.f - z) * ri + z * cs;
}

// ---------------------------------------------------------------------------
extern "C" void kernel_launch(void* const* d_in, const int* in_sizes, int n_in,
                              void* d_out, int out_size) {
    const float* vis  = (const float*)d_in[0];
    const float* lang = (const float*)d_in[1];
    const int*   adj  = (const int*)d_in[2];
    const float* mw   = (const float*)d_in[3];
    const float* mb   = (const float*)d_in[4];
    const float* rw   = (const float*)d_in[5];
    const float* rb   = (const float*)d_in[6];
    const float* uw   = (const float*)d_in[7];
    const float* ub   = (const float*)d_in[8];
    const float* ow   = (const float*)d_in[9];
    const float* ob   = (const float*)d_in[10];
    float* out = (float*)d_out;

    float* buf = nullptr;
    cudaGetSymbolAddress((void**)&buf, g_buf);
    __nv_bfloat16* wv = nullptr;
    cudaGetSymbolAddress((void**)&wv, g_wV);
    float* m = nullptr;
    cudaGetSymbolAddress((void**)&m, g_m);
    __nv_bfloat16* V0 = wv;
    __nv_bfloat16* V1 = wv + VT_STRIDE;
    __nv_bfloat16* V2 = wv + 2 * VT_STRIDE;

    static bool attr_done = false;
    if (!attr_done) {
        cudaFuncSetAttribute(wg_gemm_kernel,
                             cudaFuncAttributeMaxDynamicSharedMemorySize, WG_SMEM);
        attr_done = true;
    }

    dim3 ggrid(32, 8);                   // 1x1 gemm
    dim3 wgrid1(2, 4, NJ);               // winograd gemm, 1 conv (288 CTAs)
    dim3 wgrid2(2, 4, 2 * NJ);           // 2 convs
    dim3 wgrid3(2, 4, 3 * NJ);           // 3 convs
    dim3 itg(512), itg2(512, 1, 2);      // input transform
    dim3 inv1(512, 1), inv2(512, 2), inv3(512, 3);

    prep_kernel<<<1, 32>>>(adj);
    langbias_kernel<<<40, 256>>>(lang, mw, mb);
    tapconst_kernel<<<54, 256>>>(rw, uw, ow);
    wg_wprep_kernel<<<6144, 256>>>(rw, uw, ow);

    // V-plane = conv1x1(vis, mconv_w[:, :512])  (bias folded into b_n)
    gemm_kernel<<<ggrid, 128>>>(vis, mw, 812, 512, buf);

    // shared convs of V (x-part weights of the 3 gates): Gr, Gu, Go
    wg_itrans_kernel<<<itg, 256>>>(buf, V0, -1);
    wg_gemm_kernel<<<wgrid3, 128, WG_SMEM>>>(V0, 0, V0, 2, V0, 4, m, -1);
    wg_inv_kernel<<<inv3, 256>>>(buf + 1 * CHW, buf + 2 * CHW, buf + 3 * CHW, -1);

    // nodes in decreasing index = valid topological order (parent(i) < i)
    for (int n = NND - 1; n >= 0; n--) {
        gather_kernel<<<8192, 256>>>(n, rb);
        wg_itrans_dual_kernel<<<itg2, 256>>>(buf + 4 * CHW, V0,
                                             buf + 5 * CHW, V1, n);   // cs, rh
        wg_gemm_kernel<<<wgrid2, 128, WG_SMEM>>>(V0, 3, V1, 5, V1, 5, m, n);
        wg_inv_kernel<<<inv2, 256>>>(buf + 6 * CHW, buf + 7 * CHW,
                                     buf + 7 * CHW, n);               // U, O
        combine_kernel<<<8192, 256>>>(n, ub, ob,
                                      (n == 0) ? out : buf + (8 + n) * CHW);
        if (n > 0) {  // R[n] = conv3x3(h[n], Wr_h)
            wg_itrans_kernel<<<itg, 256>>>(buf + (8 + n) * CHW, V2, -1);
            wg_gemm_kernel<<<wgrid1, 128, WG_SMEM>>>(V2, 1, V2, 1, V2, 1, m, -1);
            wg_inv_kernel<<<inv1, 256>>>(buf + (28 + n) * CHW,
                                         buf + (28 + n) * CHW,
                                         buf + (28 + n) * CHW, -1);
        }
    }
}

// round 12
// speedup vs baseline: 3.3933x; 1.0515x over previous
#include <cuda_runtime.h>
#include <cuda_bf16.h>
#include <cstdio>
#include <cstdint>

#define NND 20
#define CHN 512
#define HH  64
#define WW  64
#define HW  4096
#define CHW 2097152   // 512*64*64
#define NT2 256       // winograd F(4,3) tiles per plane (16x16)
#define NJ  36        // 6x6 transform coefficients

// Big scratch: [V:1][Gr,Gu,Go:3][cs:1][-:3][h:20][R:20] = 48 planes
__device__ float g_buf[48ll * CHW];
__device__ float g_b[NND * CHN];            // per-node channel bias
__device__ float g_t[3 * NND * 9 * CHN];    // per-gate per-node per-tap const vectors
__device__ int   g_childcount[NND];
__device__ int   g_child[NND * NND];

// Winograd-transformed weights: [part(6)][split(2)][j(36)][o(512)][ci(512)] bf16
// parts: 0=reset_x 1=reset_h 2=update_x 3=update_h 4=output_x 5=output_h
__device__ __nv_bfloat16 g_uw[6ll * 2 * NJ * 512 * 512];
// Winograd-transformed inputs: 3 tensors, each [split(2)][j(36)][ci(512)][tile(256)]
__device__ __nv_bfloat16 g_wV[3ll * 2 * NJ * 512 * NT2];
#define VT_STRIDE (2ll * NJ * 512 * NT2)
// GEMM outputs: [conv(3)][j(36)][co(512)][tile(256)] fp32
__device__ float g_m[3ll * NJ * 512 * NT2];
#define M_STRIDE ((size_t)NJ * 512 * NT2)

__device__ __forceinline__ float sigm(float v) { return 1.f / (1.f + expf(-v)); }

// ======================= low-level helpers (sm_100-safe) ====================
__device__ __forceinline__ uint32_t smem_u32(const void* p) {
    uint32_t a;
    asm("{ .reg .u64 t; cvta.to.shared.u64 t, %1; cvt.u32.u64 %0, t; }"
        : "=r"(a) : "l"(p));
    return a;
}
__device__ __forceinline__ void cp16(uint32_t dst, const void* src) {
    asm volatile("cp.async.cg.shared.global [%0], [%1], 16;"
        :: "r"(dst), "l"(src) : "memory");
}
__device__ __forceinline__ void ldm4(uint32_t* r, uint32_t addr) {
    asm volatile("ldmatrix.sync.aligned.m8n8.x4.shared.b16 {%0,%1,%2,%3}, [%4];"
        : "=r"(r[0]), "=r"(r[1]), "=r"(r[2]), "=r"(r[3]) : "r"(addr));
}
__device__ __forceinline__ void ldm4t(uint32_t* r, uint32_t addr) {
    asm volatile("ldmatrix.sync.aligned.m8n8.x4.trans.shared.b16 {%0,%1,%2,%3}, [%4];"
        : "=r"(r[0]), "=r"(r[1]), "=r"(r[2]), "=r"(r[3]) : "r"(addr));
}
__device__ __forceinline__ void mma_bf(float* c, const uint32_t* a,
                                       uint32_t b0, uint32_t b1) {
    asm volatile(
        "mma.sync.aligned.m16n8k16.row.col.f32.bf16.bf16.f32 "
        "{%0,%1,%2,%3}, {%4,%5,%6,%7}, {%8,%9}, {%0,%1,%2,%3};"
        : "+f"(c[0]), "+f"(c[1]), "+f"(c[2]), "+f"(c[3])
        : "r"(a[0]), "r"(a[1]), "r"(a[2]), "r"(a[3]), "r"(b0), "r"(b1));
}
#define SWZ(off) ((off) ^ (((off) >> 3) & 0x70))

// ---------------------------------------------------------------------------
// Tree prep
// ---------------------------------------------------------------------------
__global__ void prep_kernel(const int* __restrict__ adj) {
    int n = threadIdx.x;
    if (n < NND) {
        int cnt = 0;
        for (int k = 0; k < NND; k++)
            if (adj[n * NND + k] != 0) g_child[n * NND + cnt++] = k;
        g_childcount[n] = cnt;
    }
}

// ---------------------------------------------------------------------------
// b[n][o] = mconv_b[o] + sum_i mconv_w[o, 512+i] * lang[n, i]
// ---------------------------------------------------------------------------
__global__ void langbias_kernel(const float* __restrict__ lang,
                                const float* __restrict__ mw,
                                const float* __restrict__ mb) {
    int idx = blockIdx.x * 256 + threadIdx.x;
    if (idx >= NND * CHN) return;
    int n = idx / CHN, o = idx - n * CHN;
    const float* wp = mw + o * 812 + 512;
    const float* lp = lang + n * 300;
    float acc = mb[o];
    for (int i = 0; i < 300; i++) acc += wp[i] * lp[i];
    g_b[idx] = acc;
}

// ---------------------------------------------------------------------------
// t[g][n][tap][o] = sum_{i<512} Wg_x[o,i,tap] * b[n][i]
// ---------------------------------------------------------------------------
__global__ void tapconst_kernel(const float* __restrict__ rw,
                                const float* __restrict__ uw,
                                const float* __restrict__ ow) {
    __shared__ float bs[NND * CHN];  // 40KB
    int tid = threadIdx.x;
    for (int idx = tid; idx < NND * CHN; idx += 256) bs[idx] = g_b[idx];
    __syncthreads();
    int gidx = blockIdx.x * 256 + tid;
    int o   = gidx & (CHN - 1);
    int tap = (gidx >> 9) % 9;
    int g   = gidx / (CHN * 9);
    const float* w = (g == 0) ? rw : (g == 1) ? uw : ow;
    const float* wp = w + o * 9216 + tap;
    float acc[NND];
#pragma unroll
    for (int n = 0; n < NND; n++) acc[n] = 0.f;
    for (int i = 0; i < CHN; i++) {
        float wv = wp[i * 9];
#pragma unroll
        for (int n = 0; n < NND; n++) acc[n] += wv * bs[n * CHN + i];
    }
#pragma unroll
    for (int n = 0; n < NND; n++)
        g_t[((g * NND + n) * 9 + tap) * CHN + o] = acc[n];
}

// ---------------------------------------------------------------------------
// F(4,3) transform primitives
// ---------------------------------------------------------------------------
__device__ __forceinline__ void gtrans(float v0, float v1, float v2, float* u) {
    u[0] = 0.25f * v0;
    u[1] = -(v0 + v1 + v2) * (1.f / 6.f);
    u[2] = (-v0 + v1 - v2) * (1.f / 6.f);
    u[3] = (v0 + 2.f * v1 + 4.f * v2) * (1.f / 24.f);
    u[4] = (v0 - 2.f * v1 + 4.f * v2) * (1.f / 24.f);
    u[5] = v2;
}
__device__ __forceinline__ void bttrans(const float* v, float* w) {
    w[0] = 4.f * v[0] - 5.f * v[2] + v[4];
    w[1] = -4.f * v[1] - 4.f * v[2] + v[3] + v[4];
    w[2] = 4.f * v[1] - 4.f * v[2] - v[3] + v[4];
    w[3] = -2.f * v[1] - v[2] + 2.f * v[3] + v[4];
    w[4] = 2.f * v[1] - v[2] - 2.f * v[3] + v[4];
    w[5] = 4.f * v[1] - 5.f * v[3] + v[5];
}
__device__ __forceinline__ void attrans(const float* v, float* y) {
    y[0] = v[0] + v[1] + v[2] + v[3] + v[4];
    y[1] = v[1] - v[2] + 2.f * (v[3] - v[4]);
    y[2] = v[1] + v[2] + 4.f * (v[3] + v[4]);
    y[3] = v[1] - v[2] + 8.f * (v[3] - v[4]) + v[5];
}
// forward transform of one 6x6 patch from padded smem plane -> V[j][ci][t] splits
__device__ __forceinline__ void fwd_write(const float (*psm)[67],
                                          __nv_bfloat16* __restrict__ V,
                                          int ci, int t) {
    int ty = t >> 4, tx = t & 15;
    float d[6][6], c[6][6];
#pragma unroll
    for (int i = 0; i < 6; i++)
#pragma unroll
        for (int j = 0; j < 6; j++)
            d[i][j] = psm[4 * ty + i][4 * tx + j];
#pragma unroll
    for (int j = 0; j < 6; j++) {
        float vin[6], vo[6];
#pragma unroll
        for (int i = 0; i < 6; i++) vin[i] = d[i][j];
        bttrans(vin, vo);
#pragma unroll
        for (int i = 0; i < 6; i++) c[i][j] = vo[i];
    }
#pragma unroll
    for (int i = 0; i < 6; i++) {
        float vo[6];
        bttrans(c[i], vo);
#pragma unroll
        for (int j = 0; j < 6; j++) {
            int j36 = i * 6 + j;
            size_t o = ((size_t)j36 * 512 + ci) * NT2 + t;
            __nv_bfloat16 h = __float2bfloat16(vo[j]);
            V[o] = h;
            V[o + (size_t)NJ * 512 * NT2] =
                __float2bfloat16(vo[j] - __bfloat162float(h));
        }
    }
}
// inverse transform of M[conv slot] at (c, t) -> 4x4 outputs
__device__ __forceinline__ void inv_read(const float* __restrict__ M,
                                         int c, int t, float y16[4][4]) {
    float Z[6][6];
#pragma unroll
    for (int i = 0; i < 6; i++)
#pragma unroll
        for (int j = 0; j < 6; j++)
            Z[i][j] = M[((size_t)(i * 6 + j) * 512 + c) * NT2 + t];
    float cc[4][6];
#pragma unroll
    for (int j = 0; j < 6; j++) {
        float vin[6], vo[4];
#pragma unroll
        for (int i = 0; i < 6; i++) vin[i] = Z[i][j];
        attrans(vin, vo);
#pragma unroll
        for (int i = 0; i < 4; i++) cc[i][j] = vo[i];
    }
#pragma unroll
    for (int i = 0; i < 4; i++) attrans(cc[i], y16[i]);
}

// ---------------------------------------------------------------------------
// F(4,3) weight transform: U = G g G^T (6x6), split hi/lo bf16.
// ---------------------------------------------------------------------------
__global__ void wg_wprep_kernel(const float* __restrict__ rw,
                                const float* __restrict__ uw,
                                const float* __restrict__ ow) {
    int idx = blockIdx.x * 256 + threadIdx.x;
    if (idx >= 6 * 512 * 512) return;
    int ci = idx & 511;
    int o  = (idx >> 9) & 511;
    int part = idx >> 18;
    const float* w = (part < 2) ? rw : (part < 4) ? uw : ow;
    int coff = (part & 1) << 9;
    const float* gp = w + (size_t)o * 9216 + (size_t)(coff + ci) * 9;
    float g[9];
#pragma unroll
    for (int k = 0; k < 9; k++) g[k] = gp[k];
    float a[6][3];
#pragma unroll
    for (int j = 0; j < 3; j++) {
        float u[6];
        gtrans(g[j], g[3 + j], g[6 + j], u);
#pragma unroll
        for (int i = 0; i < 6; i++) a[i][j] = u[i];
    }
#pragma unroll
    for (int i = 0; i < 6; i++) {
        float U[6];
        gtrans(a[i][0], a[i][1], a[i][2], U);
#pragma unroll
        for (int j = 0; j < 6; j++) {
            int j36 = i * 6 + j;
            size_t base = ((((size_t)(part * 2) * NJ + j36) * 512 + o) << 9) + ci;
            __nv_bfloat16 h = __float2bfloat16(U[j]);
            g_uw[base] = h;
            g_uw[base + (size_t)NJ * 512 * 512] =
                __float2bfloat16(U[j] - __bfloat162float(h));
        }
    }
}

// ---------------------------------------------------------------------------
// Plain input transform (for the initial V-plane): src[ci][64][64] -> V splits
// ---------------------------------------------------------------------------
__global__ void wg_itrans_kernel(const float* __restrict__ src,
                                 __nv_bfloat16* __restrict__ V) {
    __shared__ float psm[66][67];
    int ci = blockIdx.x, tid = threadIdx.x;
    const float* sp = src + (size_t)ci * HW;
    for (int i = tid; i < 66 * 67; i += 256) (&psm[0][0])[i] = 0.f;
    __syncthreads();
    for (int i = tid; i < 4096; i += 256)
        psm[(i >> 6) + 1][(i & 63) + 1] = sp[i];
    __syncthreads();
    fwd_write(psm, V, ci, tid);
}

// ---------------------------------------------------------------------------
// FUSED gather + dual forward transform (internal nodes only).
// Per-ci block: cs/rh from Gr,h[k],R[k]; writes cs plane + V0 (cs) + V1 (rh).
// ---------------------------------------------------------------------------
__global__ void gather_itrans_kernel(int n, const float* __restrict__ rb,
                                     __nv_bfloat16* __restrict__ V0,
                                     __nv_bfloat16* __restrict__ V1) {
    int cnt = g_childcount[n];
    if (cnt == 0) return;
    __shared__ float csm[66][67];
    __shared__ float rsm[66][67];
    int ci = blockIdx.x, tid = threadIdx.x;
    for (int i = tid; i < 66 * 67; i += 256) {
        (&csm[0][0])[i] = 0.f;
        (&rsm[0][0])[i] = 0.f;
    }
    __syncthreads();
    float tv[9];
#pragma unroll
    for (int k = 0; k < 9; k++)
        tv[k] = g_t[((0 * NND + n) * 9 + k) * CHN + ci];
    float rbc = rb[ci];
    const float* Gr = g_buf + 1 * CHW + (size_t)ci * HW;
    float* csout = g_buf + 4 * CHW + (size_t)ci * HW;
    for (int p = tid; p < HW; p += 256) {
        int y = p >> 6, x = p & 63;
        int ky0 = (y == 0), ky1 = 2 - (y == HH - 1);
        int kx0 = (x == 0), kx1 = 2 - (x == WW - 1);
        float cr = 0.f;
        for (int ky = ky0; ky <= ky1; ky++)
            for (int kx = kx0; kx <= kx1; kx++)
                cr += tv[ky * 3 + kx];
        float base = Gr[p] + rbc + cr;
        float cs = 0.f, rh = 0.f;
        for (int j = 0; j < cnt; j++) {
            int k = g_child[n * NND + j];
            float hv = g_buf[(size_t)(8 + k) * CHW + (size_t)ci * HW + p];
            float rr = sigm(base + g_buf[(size_t)(28 + k) * CHW + (size_t)ci * HW + p]);
            cs += hv;
            rh += rr * hv;
        }
        csout[p] = cs;
        csm[y + 1][x + 1] = cs;
        rsm[y + 1][x + 1] = rh;
    }
    __syncthreads();
    fwd_write(csm, V0, ci, tid);
    fwd_write(rsm, V1, ci, tid);
}

// ---------------------------------------------------------------------------
// FUSED inverse(U,O) + combine + forward transform of h (all nodes).
// Per-channel block. Root (n==0): writes out, no transform.
// ---------------------------------------------------------------------------
__global__ void inv_combine_kernel(int n, const float* __restrict__ ub,
                                   const float* __restrict__ ob,
                                   float* __restrict__ outroot,
                                   __nv_bfloat16* __restrict__ V2) {
    __shared__ float hsm[66][67];
    int c = blockIdx.x, tid = threadIdx.x;
    bool haskids = g_childcount[n] > 0;
    for (int i = tid; i < 66 * 67; i += 256) (&hsm[0][0])[i] = 0.f;
    __syncthreads();
    int t = tid, ty = t >> 4, tx = t & 15;
    float u16[4][4], o16[4][4];
    if (haskids) {
        inv_read(g_m, c, t, u16);
        inv_read(g_m + M_STRIDE, c, t, o16);
    }
    float tu9[9], to9[9];
#pragma unroll
    for (int k = 0; k < 9; k++) {
        tu9[k] = g_t[((1 * NND + n) * 9 + k) * CHN + c];
        to9[k] = g_t[((2 * NND + n) * 9 + k) * CHN + c];
    }
    float ubc = ub[c], obc = ob[c];
    const float* Gu = g_buf + 2 * CHW + (size_t)c * HW;
    const float* Go = g_buf + 3 * CHW + (size_t)c * HW;
    const float* CS = g_buf + 4 * CHW + (size_t)c * HW;
    float* hpl = (n == 0) ? (outroot + (size_t)c * HW)
                          : (g_buf + (size_t)(8 + n) * CHW + (size_t)c * HW);
#pragma unroll
    for (int i = 0; i < 4; i++) {
#pragma unroll
        for (int j = 0; j < 4; j++) {
            int y = 4 * ty + i, x = 4 * tx + j;
            int p = y * WW + x;
            int ky0 = (y == 0), ky1 = 2 - (y == HH - 1);
            int kx0 = (x == 0), kx1 = 2 - (x == WW - 1);
            float cu = 0.f, co = 0.f;
            for (int ky = ky0; ky <= ky1; ky++)
                for (int kx = kx0; kx <= kx1; kx++) {
                    cu += tu9[ky * 3 + kx];
                    co += to9[ky * 3 + kx];
                }
            float uacc = haskids ? u16[i][j] : 0.f;
            float oacc = haskids ? o16[i][j] : 0.f;
            float cs   = haskids ? CS[p] : 0.f;
            float z  = sigm(Gu[p] + ubc + cu + uacc);
            float ri = tanhf(Go[p] + obc + co + oacc);
            float h = (1.f - z) * ri + z * cs;
            hpl[p] = h;
            hsm[y + 1][x + 1] = h;
        }
    }
    if (n > 0) {
        __syncthreads();
        fwd_write(hsm, V2, c, t);
    }
}

// ---------------------------------------------------------------------------
// GEMM: V = vis @ W_vis  (1x1 conv), fp32
// ---------------------------------------------------------------------------
__global__ __launch_bounds__(128) void gemm_kernel(
    const float* __restrict__ in, const float* __restrict__ w,
    int ldw, int K, float* __restrict__ out) {
    __shared__ float xs[8 * 128];
    __shared__ float wsm[8 * 65];
    int pB  = blockIdx.x * 128;
    int coB = blockIdx.y * 64;
    int tid = threadIdx.x;
    int pxg = tid & 15, cog = tid >> 4;
    float acc[8][8];
#pragma unroll
    for (int a = 0; a < 8; a++)
#pragma unroll
        for (int b = 0; b < 8; b++) acc[a][b] = 0.f;
    for (int kb = 0; kb < K; kb += 8) {
        __syncthreads();
        for (int idx = tid; idx < 1024; idx += 128) {
            int i = idx >> 7, p = idx & 127;
            xs[idx] = in[(kb + i) * HW + pB + p];
        }
        for (int idx = tid; idx < 512; idx += 128) {
            int co = idx >> 3, i = idx & 7;
            wsm[i * 65 + co] = w[(coB + co) * ldw + kb + i];
        }
        __syncthreads();
#pragma unroll
        for (int i = 0; i < 8; i++) {
            float xv[8], wv[8];
#pragma unroll
            for (int v = 0; v < 8; v++) xv[v] = xs[i * 128 + pxg + 16 * v];
#pragma unroll
            for (int u = 0; u < 8; u++) wv[u] = wsm[i * 65 + u * 8 + cog];
#pragma unroll
            for (int u = 0; u < 8; u++)
#pragma unroll
                for (int v = 0; v < 8; v++)
                    acc[u][v] = fmaf(wv[u], xv[v], acc[u][v]);
        }
    }
#pragma unroll
    for (int u = 0; u < 8; u++) {
        float* op = out + (coB + u * 8 + cog) * HW + pB + pxg;
#pragma unroll
        for (int v = 0; v < 8; v++) op[16 * v] = acc[u][v];
    }
}

// ---------------------------------------------------------------------------
// Winograd GEMM: per j, M_j[co][tile] = U_j[co][ci] * V_j[ci][tile]
// bf16 3-split, fp32 accum. K=512 -> 24 stages of 64.
// CTA 128co x 128tile, 4 warps (2m x 2n). grid (2, 4, 36*nconv).
// ---------------------------------------------------------------------------
#define WG_SMEM 98304   // 3 x (A 16KB + B 16KB)

__device__ __forceinline__ void wg_issue_stage(
    int s, uint32_t sA, int tid, int tileB, int coB, int part, int j,
    const __nv_bfloat16* V) {
    int s3 = s >> 3;                 // 0,1,2 split term
    int cb = (s & 7) << 6;
    int wsplit = (s3 == 1) ? 1 : 0;
    int xsplit = (s3 == 2) ? 1 : 0;
    const __nv_bfloat16* Abase =
        g_uw + ((((size_t)(part * 2 + wsplit) * NJ + j) * 512 + coB) << 9) + cb;
    const __nv_bfloat16* Bbase =
        V + (((size_t)(xsplit * NJ + j) * 512 + cb) * NT2) + tileB;
    uint32_t slot = sA + (s % 3) * 32768;
#pragma unroll
    for (int it = 0; it < 8; it++) {
        int i = tid + it * 128;
        int o = i >> 3, q = i & 7;
        cp16(slot + SWZ(o * 128 + q * 16), Abase + ((size_t)o << 9) + q * 8);
    }
#pragma unroll
    for (int it = 0; it < 8; it++) {
        int i = tid + it * 128;
        int k = i >> 4, cc = i & 15;
        cp16(slot + 16384 + k * 256 + ((cc ^ (k & 7)) << 4),
             Bbase + (size_t)k * NT2 + cc * 8);
    }
    asm volatile("cp.async.commit_group;" ::: "memory");
}

__global__ __launch_bounds__(128)
void wg_gemm_kernel(const __nv_bfloat16* __restrict__ V0, int p0,
                    const __nv_bfloat16* __restrict__ V1, int p1,
                    const __nv_bfloat16* __restrict__ V2, int p2,
                    float* __restrict__ Mbase, int flag_n) {
    if (flag_n >= 0 && g_childcount[flag_n] == 0) return;
    extern __shared__ char smem[];
    uint32_t sA = smem_u32(smem);
    int which = blockIdx.z / NJ;
    int j = blockIdx.z - which * NJ;
    const __nv_bfloat16* V = (which == 0) ? V0 : (which == 1) ? V1 : V2;
    int part = (which == 0) ? p0 : (which == 1) ? p1 : p2;
    float* M = Mbase + (size_t)which * M_STRIDE;

    int tid = threadIdx.x;
    int wid = tid >> 5, lane = tid & 31;
    int tileB = blockIdx.x * 128;
    int coB   = blockIdx.y * 128;
    int wm = wid >> 1;
    int wn = wid & 1;

    float acc[4][8][4];
#pragma unroll
    for (int a = 0; a < 4; a++)
#pragma unroll
        for (int b = 0; b < 8; b++)
#pragma unroll
            for (int c = 0; c < 4; c++) acc[a][b][c] = 0.f;

    wg_issue_stage(0, sA, tid, tileB, coB, part, j, V);
    wg_issue_stage(1, sA, tid, tileB, coB, part, j, V);

    for (int s = 0; s < 24; s++) {
        asm volatile("cp.async.wait_group 1;" ::: "memory");
        __syncthreads();
        if (s + 2 < 24)
            wg_issue_stage(s + 2, sA, tid, tileB, coB, part, j, V);
        uint32_t Ab = sA + (s % 3) * 32768;
        uint32_t Bb = Ab + 16384;
#pragma unroll
        for (int ks = 0; ks < 4; ks++) {
            uint32_t afr[4][4];
#pragma unroll
            for (int mi = 0; mi < 4; mi++) {
                int row = wm * 64 + mi * 16 + (lane & 15);
                int k16 = ks * 2 + (lane >> 4);
                ldm4(afr[mi], Ab + SWZ(row * 128 + k16 * 16));
            }
            uint32_t bfr[4][4];
#pragma unroll
            for (int ng = 0; ng < 4; ng++) {
                int krow = ks * 16 + (lane & 7) + (((lane >> 3) & 1) << 3);
                int cc   = ((wn * 64 + ng * 16) >> 3) + (lane >> 4);
                ldm4t(bfr[ng], Bb + krow * 256 + ((cc ^ (krow & 7)) << 4));
            }
#pragma unroll
            for (int mi = 0; mi < 4; mi++)
#pragma unroll
                for (int ng = 0; ng < 4; ng++) {
                    mma_bf(acc[mi][ng * 2 + 0], afr[mi], bfr[ng][0], bfr[ng][1]);
                    mma_bf(acc[mi][ng * 2 + 1], afr[mi], bfr[ng][2], bfr[ng][3]);
                }
        }
        __syncthreads();
    }

#pragma unroll
    for (int mi = 0; mi < 4; mi++) {
        int row0 = coB + wm * 64 + mi * 16 + (lane >> 2);
        float* mp0 = M + ((size_t)j * 512 + row0) * NT2 + tileB;
#pragma unroll
        for (int nj = 0; nj < 8; nj++) {
            int col = wn * 64 + nj * 8 + (lane & 3) * 2;
            *reinterpret_cast<float2*>(mp0 + col) =
                make_float2(acc[mi][nj][0], acc[mi][nj][1]);
            *reinterpret_cast<float2*>(mp0 + 8 * NT2 + col) =
                make_float2(acc[mi][nj][2], acc[mi][nj][3]);
        }
    }
}

// ---------------------------------------------------------------------------
// Plain inverse transform (initial Gr/Gu/Go convs, and per-node R conv)
// grid (512, nconv), 256 threads
// ---------------------------------------------------------------------------
__global__ void wg_inv_kernel(float* __restrict__ D0, float* __restrict__ D1,
                              float* __restrict__ D2, int flag_n) {
    if (flag_n >= 0 && g_childcount[flag_n] == 0) return;
    int conv = blockIdx.y;
    const float* M = g_m + (size_t)conv * M_STRIDE;
    float* D = (conv == 0) ? D0 : (conv == 1) ? D1 : D2;
    int e = blockIdx.x * 256 + threadIdx.x;
    int co = e >> 8, t = e & (NT2 - 1);
    float y16[4][4];
    inv_read(M, co, t, y16);
    int ty = t >> 4, tx = t & 15;
    float* op = D + (size_t)co * HW + (4 * ty) * WW + 4 * tx;
#pragma unroll
    for (int i = 0; i < 4; i++)
        *reinterpret_cast<float4*>(op + i * WW) =
            make_float4(y16[i][0], y16[i][1], y16[i][2], y16[i][3]);
}

// ---------------------------------------------------------------------------
extern "C" void kernel_launch(void* const* d_in, const int* in_sizes, int n_in,
                              void* d_out, int out_size) {
    const float* vis  = (const float*)d_in[0];
    const float* lang = (const float*)d_in[1];
    const int*   adj  = (const int*)d_in[2];
    const float* mw   = (const float*)d_in[3];
    const float* mb   = (const float*)d_in[4];
    const float* rw   = (const float*)d_in[5];
    const float* rb   = (const float*)d_in[6];
    const float* uw   = (const float*)d_in[7];
    const float* ub   = (const float*)d_in[8];
    const float* ow   = (const float*)d_in[9];
    const float* ob   = (const float*)d_in[10];
    float* out = (float*)d_out;

    float* buf = nullptr;
    cudaGetSymbolAddress((void**)&buf, g_buf);
    __nv_bfloat16* wv = nullptr;
    cudaGetSymbolAddress((void**)&wv, g_wV);
    float* m = nullptr;
    cudaGetSymbolAddress((void**)&m, g_m);
    __nv_bfloat16* V0 = wv;
    __nv_bfloat16* V1 = wv + VT_STRIDE;
    __nv_bfloat16* V2 = wv + 2 * VT_STRIDE;

    static bool attr_done = false;
    if (!attr_done) {
        cudaFuncSetAttribute(wg_gemm_kernel,
                             cudaFuncAttributeMaxDynamicSharedMemorySize, WG_SMEM);
        attr_done = true;
    }

    dim3 ggrid(32, 8);                   // 1x1 gemm
    dim3 wgrid1(2, 4, NJ);               // winograd gemm, 1 conv
    dim3 wgrid2(2, 4, 2 * NJ);           // 2 convs
    dim3 wgrid3(2, 4, 3 * NJ);           // 3 convs
    dim3 inv1(512, 1), inv3(512, 3);

    prep_kernel<<<1, 32>>>(adj);
    langbias_kernel<<<40, 256>>>(lang, mw, mb);
    tapconst_kernel<<<54, 256>>>(rw, uw, ow);
    wg_wprep_kernel<<<6144, 256>>>(rw, uw, ow);

    // V-plane = conv1x1(vis, mconv_w[:, :512])  (bias folded into b_n)
    gemm_kernel<<<ggrid, 128>>>(vis, mw, 812, 512, buf);

    // shared convs of V (x-part weights of the 3 gates): Gr, Gu, Go
    wg_itrans_kernel<<<512, 256>>>(buf, V0);
    wg_gemm_kernel<<<wgrid3, 128, WG_SMEM>>>(V0, 0, V0, 2, V0, 4, m, -1);
    wg_inv_kernel<<<inv3, 256>>>(buf + 1 * CHW, buf + 2 * CHW, buf + 3 * CHW, -1);

    // nodes in decreasing index = valid topological order (parent(i) < i)
    for (int n = NND - 1; n >= 0; n--) {
        // fused gather + forward transforms of cs, rh (skips on leaf)
        gather_itrans_kernel<<<512, 256>>>(n, rb, V0, V1);
        // U = conv(cs, Wu_h), O = conv(rh, Wo_h) (skips on leaf)
        wg_gemm_kernel<<<wgrid2, 128, WG_SMEM>>>(V0, 3, V1, 5, V1, 5, m, n);
        // fused inverse(U,O) + combine (+ forward transform of h when n>0)
        inv_combine_kernel<<<512, 256>>>(n, ub, ob, out, V2);
        if (n > 0) {  // R[n] = conv3x3(h[n], Wr_h)
            wg_gemm_kernel<<<wgrid1, 128, WG_SMEM>>>(V2, 1, V2, 1, V2, 1, m, -1);
            wg_inv_kernel<<<inv1, 256>>>(buf + (size_t)(28 + n) * CHW,
                                         buf + (size_t)(28 + n) * CHW,
                                         buf + (size_t)(28 + n) * CHW, -1);
        }
    }
}

// round 13
// speedup vs baseline: 3.9905x; 1.1760x over previous
#include <cuda_runtime.h>
#include <cuda_bf16.h>
#include <cstdio>
#include <cstdint>

#define NND 20
#define CHN 512
#define HH  64
#define WW  64
#define HW  4096
#define CHW 2097152   // 512*64*64
#define NT2 256       // winograd F(4,3) tiles per plane (16x16)
#define NJ  36        // 6x6 transform coefficients

// Scratch planes: [V:1][Gr,Gu,Go:3][cs:1][-:3][h:20] = 28 planes
__device__ float g_buf[28ll * CHW];
__device__ float g_b[NND * CHN];            // per-node channel bias
__device__ float g_t[3 * NND * 9 * CHN];    // per-gate per-node per-tap const vectors
__device__ int   g_childcount[NND];
__device__ int   g_child[NND * NND];

// Winograd-transformed weights: [part(6)][split(2)][j(36)][o(512)][ci(512)] bf16
// parts: 0=reset_x 1=reset_h 2=update_x 3=update_h 4=output_x 5=output_h
__device__ __nv_bfloat16 g_uw[6ll * 2 * NJ * 512 * 512];
// Winograd-transformed inputs: 3 tensors, each [split(2)][j(36)][ci(512)][tile(256)]
__device__ __nv_bfloat16 g_wV[3ll * 2 * NJ * 512 * NT2];
#define VT_STRIDE (2ll * NJ * 512 * NT2)
// GEMM outputs: [conv(3)][j(36)][co(512)][tile(256)] fp32
__device__ float g_m[3ll * NJ * 512 * NT2];
#define M_STRIDE ((size_t)NJ * 512 * NT2)
// Per-node Winograd-domain R-conv results (kept until parent's gather)
__device__ float g_mr[(size_t)NND * NJ * 512 * NT2];
// mconv (1x1) bf16 split operands
__device__ __nv_bfloat16 g_vs[2ll * CHW];          // vis splits [split][ci][px]
__device__ __nv_bfloat16 g_mwsp[2ll * 512 * 512];  // mconv W splits [split][o][ci]

__device__ __forceinline__ float sigm(float v) { return 1.f / (1.f + expf(-v)); }

// ======================= low-level helpers (sm_100-safe) ====================
__device__ __forceinline__ uint32_t smem_u32(const void* p) {
    uint32_t a;
    asm("{ .reg .u64 t; cvta.to.shared.u64 t, %1; cvt.u32.u64 %0, t; }"
        : "=r"(a) : "l"(p));
    return a;
}
__device__ __forceinline__ void cp16(uint32_t dst, const void* src) {
    asm volatile("cp.async.cg.shared.global [%0], [%1], 16;"
        :: "r"(dst), "l"(src) : "memory");
}
__device__ __forceinline__ void ldm4(uint32_t* r, uint32_t addr) {
    asm volatile("ldmatrix.sync.aligned.m8n8.x4.shared.b16 {%0,%1,%2,%3}, [%4];"
        : "=r"(r[0]), "=r"(r[1]), "=r"(r[2]), "=r"(r[3]) : "r"(addr));
}
__device__ __forceinline__ void ldm4t(uint32_t* r, uint32_t addr) {
    asm volatile("ldmatrix.sync.aligned.m8n8.x4.trans.shared.b16 {%0,%1,%2,%3}, [%4];"
        : "=r"(r[0]), "=r"(r[1]), "=r"(r[2]), "=r"(r[3]) : "r"(addr));
}
__device__ __forceinline__ void mma_bf(float* c, const uint32_t* a,
                                       uint32_t b0, uint32_t b1) {
    asm volatile(
        "mma.sync.aligned.m16n8k16.row.col.f32.bf16.bf16.f32 "
        "{%0,%1,%2,%3}, {%4,%5,%6,%7}, {%8,%9}, {%0,%1,%2,%3};"
        : "+f"(c[0]), "+f"(c[1]), "+f"(c[2]), "+f"(c[3])
        : "r"(a[0]), "r"(a[1]), "r"(a[2]), "r"(a[3]), "r"(b0), "r"(b1));
}
#define SWZ(off) ((off) ^ (((off) >> 3) & 0x70))

// ---------------------------------------------------------------------------
// Tree prep
// ---------------------------------------------------------------------------
__global__ void prep_kernel(const int* __restrict__ adj) {
    int n = threadIdx.x;
    if (n < NND) {
        int cnt = 0;
        for (int k = 0; k < NND; k++)
            if (adj[n * NND + k] != 0) g_child[n * NND + cnt++] = k;
        g_childcount[n] = cnt;
    }
}

// ---------------------------------------------------------------------------
// b[n][o] = mconv_b[o] + sum_i mconv_w[o, 512+i] * lang[n, i]
// ---------------------------------------------------------------------------
__global__ void langbias_kernel(const float* __restrict__ lang,
                                const float* __restrict__ mw,
                                const float* __restrict__ mb) {
    int idx = blockIdx.x * 256 + threadIdx.x;
    if (idx >= NND * CHN) return;
    int n = idx / CHN, o = idx - n * CHN;
    const float* wp = mw + o * 812 + 512;
    const float* lp = lang + n * 300;
    float acc = mb[o];
    for (int i = 0; i < 300; i++) acc += wp[i] * lp[i];
    g_b[idx] = acc;
}

// ---------------------------------------------------------------------------
// t[g][n][tap][o] = sum_{i<512} Wg_x[o,i,tap] * b[n][i]
// ---------------------------------------------------------------------------
__global__ void tapconst_kernel(const float* __restrict__ rw,
                                const float* __restrict__ uw,
                                const float* __restrict__ ow) {
    __shared__ float bs[NND * CHN];  // 40KB
    int tid = threadIdx.x;
    for (int idx = tid; idx < NND * CHN; idx += 256) bs[idx] = g_b[idx];
    __syncthreads();
    int gidx = blockIdx.x * 256 + tid;
    int o   = gidx & (CHN - 1);
    int tap = (gidx >> 9) % 9;
    int g   = gidx / (CHN * 9);
    const float* w = (g == 0) ? rw : (g == 1) ? uw : ow;
    const float* wp = w + o * 9216 + tap;
    float acc[NND];
#pragma unroll
    for (int n = 0; n < NND; n++) acc[n] = 0.f;
    for (int i = 0; i < CHN; i++) {
        float wv = wp[i * 9];
#pragma unroll
        for (int n = 0; n < NND; n++) acc[n] += wv * bs[n * CHN + i];
    }
#pragma unroll
    for (int n = 0; n < NND; n++)
        g_t[((g * NND + n) * 9 + tap) * CHN + o] = acc[n];
}

// ---------------------------------------------------------------------------
// F(4,3) transform primitives
// ---------------------------------------------------------------------------
__device__ __forceinline__ void gtrans(float v0, float v1, float v2, float* u) {
    u[0] = 0.25f * v0;
    u[1] = -(v0 + v1 + v2) * (1.f / 6.f);
    u[2] = (-v0 + v1 - v2) * (1.f / 6.f);
    u[3] = (v0 + 2.f * v1 + 4.f * v2) * (1.f / 24.f);
    u[4] = (v0 - 2.f * v1 + 4.f * v2) * (1.f / 24.f);
    u[5] = v2;
}
__device__ __forceinline__ void bttrans(const float* v, float* w) {
    w[0] = 4.f * v[0] - 5.f * v[2] + v[4];
    w[1] = -4.f * v[1] - 4.f * v[2] + v[3] + v[4];
    w[2] = 4.f * v[1] - 4.f * v[2] - v[3] + v[4];
    w[3] = -2.f * v[1] - v[2] + 2.f * v[3] + v[4];
    w[4] = 2.f * v[1] - v[2] - 2.f * v[3] + v[4];
    w[5] = 4.f * v[1] - 5.f * v[3] + v[5];
}
__device__ __forceinline__ void attrans(const float* v, float* y) {
    y[0] = v[0] + v[1] + v[2] + v[3] + v[4];
    y[1] = v[1] - v[2] + 2.f * (v[3] - v[4]);
    y[2] = v[1] + v[2] + 4.f * (v[3] + v[4]);
    y[3] = v[1] - v[2] + 8.f * (v[3] - v[4]) + v[5];
}
__device__ __forceinline__ void fwd_write(const float (*psm)[67],
                                          __nv_bfloat16* __restrict__ V,
                                          int ci, int t) {
    int ty = t >> 4, tx = t & 15;
    float d[6][6], c[6][6];
#pragma unroll
    for (int i = 0; i < 6; i++)
#pragma unroll
        for (int j = 0; j < 6; j++)
            d[i][j] = psm[4 * ty + i][4 * tx + j];
#pragma unroll
    for (int j = 0; j < 6; j++) {
        float vin[6], vo[6];
#pragma unroll
        for (int i = 0; i < 6; i++) vin[i] = d[i][j];
        bttrans(vin, vo);
#pragma unroll
        for (int i = 0; i < 6; i++) c[i][j] = vo[i];
    }
#pragma unroll
    for (int i = 0; i < 6; i++) {
        float vo[6];
        bttrans(c[i], vo);
#pragma unroll
        for (int j = 0; j < 6; j++) {
            int j36 = i * 6 + j;
            size_t o = ((size_t)j36 * 512 + ci) * NT2 + t;
            __nv_bfloat16 h = __float2bfloat16(vo[j]);
            V[o] = h;
            V[o + (size_t)NJ * 512 * NT2] =
                __float2bfloat16(vo[j] - __bfloat162float(h));
        }
    }
}
__device__ __forceinline__ void inv_read(const float* __restrict__ M,
                                         int c, int t, float y16[4][4]) {
    float Z[6][6];
#pragma unroll
    for (int i = 0; i < 6; i++)
#pragma unroll
        for (int j = 0; j < 6; j++)
            Z[i][j] = M[((size_t)(i * 6 + j) * 512 + c) * NT2 + t];
    float cc[4][6];
#pragma unroll
    for (int j = 0; j < 6; j++) {
        float vin[6], vo[4];
#pragma unroll
        for (int i = 0; i < 6; i++) vin[i] = Z[i][j];
        attrans(vin, vo);
#pragma unroll
        for (int i = 0; i < 4; i++) cc[i][j] = vo[i];
    }
#pragma unroll
    for (int i = 0; i < 4; i++) attrans(cc[i], y16[i]);
}

// ---------------------------------------------------------------------------
// F(4,3) weight transform: U = G g G^T (6x6), split hi/lo bf16.
// ---------------------------------------------------------------------------
__global__ void wg_wprep_kernel(const float* __restrict__ rw,
                                const float* __restrict__ uw,
                                const float* __restrict__ ow) {
    int idx = blockIdx.x * 256 + threadIdx.x;
    if (idx >= 6 * 512 * 512) return;
    int ci = idx & 511;
    int o  = (idx >> 9) & 511;
    int part = idx >> 18;
    const float* w = (part < 2) ? rw : (part < 4) ? uw : ow;
    int coff = (part & 1) << 9;
    const float* gp = w + (size_t)o * 9216 + (size_t)(coff + ci) * 9;
    float g[9];
#pragma unroll
    for (int k = 0; k < 9; k++) g[k] = gp[k];
    float a[6][3];
#pragma unroll
    for (int j = 0; j < 3; j++) {
        float u[6];
        gtrans(g[j], g[3 + j], g[6 + j], u);
#pragma unroll
        for (int i = 0; i < 6; i++) a[i][j] = u[i];
    }
#pragma unroll
    for (int i = 0; i < 6; i++) {
        float U[6];
        gtrans(a[i][0], a[i][1], a[i][2], U);
#pragma unroll
        for (int j = 0; j < 6; j++) {
            int j36 = i * 6 + j;
            size_t base = ((((size_t)(part * 2) * NJ + j36) * 512 + o) << 9) + ci;
            __nv_bfloat16 h = __float2bfloat16(U[j]);
            g_uw[base] = h;
            g_uw[base + (size_t)NJ * 512 * 512] =
                __float2bfloat16(U[j] - __bfloat162float(h));
        }
    }
}

// ---------------------------------------------------------------------------
// mconv operand splits
// ---------------------------------------------------------------------------
__global__ void vis_split_kernel(const float* __restrict__ vis) {
    int i = blockIdx.x * 256 + threadIdx.x;
    if (i >= CHW) return;
    float v = vis[i];
    __nv_bfloat16 h = __float2bfloat16(v);
    g_vs[i] = h;
    g_vs[(size_t)CHW + i] = __float2bfloat16(v - __bfloat162float(h));
}
__global__ void mw_split_kernel(const float* __restrict__ mw) {
    int i = blockIdx.x * 256 + threadIdx.x;
    if (i >= 512 * 512) return;
    int o = i >> 9, ci = i & 511;
    float v = mw[o * 812 + ci];
    __nv_bfloat16 h = __float2bfloat16(v);
    g_mwsp[i] = h;
    g_mwsp[262144 + i] = __float2bfloat16(v - __bfloat162float(h));
}

// ---------------------------------------------------------------------------
// Plain input transform (for the initial V-plane): src[ci][64][64] -> V splits
// ---------------------------------------------------------------------------
__global__ void wg_itrans_kernel(const float* __restrict__ src,
                                 __nv_bfloat16* __restrict__ V) {
    __shared__ float psm[66][67];
    int ci = blockIdx.x, tid = threadIdx.x;
    const float* sp = src + (size_t)ci * HW;
    for (int i = tid; i < 66 * 67; i += 256) (&psm[0][0])[i] = 0.f;
    __syncthreads();
    for (int i = tid; i < 4096; i += 256)
        psm[(i >> 6) + 1][(i & 63) + 1] = sp[i];
    __syncthreads();
    fwd_write(psm, V, ci, tid);
}

// ---------------------------------------------------------------------------
// FUSED gather (with on-the-fly R inverse transform) + dual forward transform.
// Per-ci block, internal nodes only. Writes cs plane + V0 (cs) + V1 (rh).
// ---------------------------------------------------------------------------
__global__ void gather_itrans_kernel(int n, const float* __restrict__ rb,
                                     __nv_bfloat16* __restrict__ V0,
                                     __nv_bfloat16* __restrict__ V1) {
    int cnt = g_childcount[n];
    if (cnt == 0) return;
    __shared__ float csm[66][67];
    __shared__ float rsm[66][67];
    int ci = blockIdx.x, tid = threadIdx.x;
    for (int i = tid; i < 66 * 67; i += 256) {
        (&csm[0][0])[i] = 0.f;
        (&rsm[0][0])[i] = 0.f;
    }
    __syncthreads();
    float tv[9];
#pragma unroll
    for (int k = 0; k < 9; k++)
        tv[k] = g_t[((0 * NND + n) * 9 + k) * CHN + ci];
    float rbc = rb[ci];
    int ty = tid >> 4, tx = tid & 15;
    const float* Gr = g_buf + 1 * CHW + (size_t)ci * HW;
    float base16[4][4];
#pragma unroll
    for (int i = 0; i < 4; i++)
#pragma unroll
        for (int j = 0; j < 4; j++) {
            int y = 4 * ty + i, x = 4 * tx + j;
            int ky0 = (y == 0), ky1 = 2 - (y == HH - 1);
            int kx0 = (x == 0), kx1 = 2 - (x == WW - 1);
            float cr = 0.f;
            for (int ky = ky0; ky <= ky1; ky++)
                for (int kx = kx0; kx <= kx1; kx++)
                    cr += tv[ky * 3 + kx];
            base16[i][j] = Gr[y * WW + x] + rbc + cr;
        }
    float cs16[4][4], rh16[4][4];
#pragma unroll
    for (int i = 0; i < 4; i++)
#pragma unroll
        for (int j = 0; j < 4; j++) { cs16[i][j] = 0.f; rh16[i][j] = 0.f; }
    for (int c0 = 0; c0 < cnt; c0++) {
        int k = g_child[n * NND + c0];
        float r16[4][4];
        inv_read(g_mr + (size_t)k * M_STRIDE, ci, tid, r16);
        const float* hp = g_buf + (size_t)(8 + k) * CHW + (size_t)ci * HW;
#pragma unroll
        for (int i = 0; i < 4; i++) {
            float4 hv4 = *reinterpret_cast<const float4*>(
                hp + (4 * ty + i) * WW + 4 * tx);
            float hv[4] = {hv4.x, hv4.y, hv4.z, hv4.w};
#pragma unroll
            for (int j = 0; j < 4; j++) {
                float rr = sigm(base16[i][j] + r16[i][j]);
                cs16[i][j] += hv[j];
                rh16[i][j] += rr * hv[j];
            }
        }
    }
    float* csout = g_buf + 4 * CHW + (size_t)ci * HW;
#pragma unroll
    for (int i = 0; i < 4; i++) {
        int y = 4 * ty + i;
        *reinterpret_cast<float4*>(csout + y * WW + 4 * tx) =
            make_float4(cs16[i][0], cs16[i][1], cs16[i][2], cs16[i][3]);
#pragma unroll
        for (int j = 0; j < 4; j++) {
            csm[y + 1][4 * tx + j + 1] = cs16[i][j];
            rsm[y + 1][4 * tx + j + 1] = rh16[i][j];
        }
    }
    __syncthreads();
    fwd_write(csm, V0, ci, tid);
    fwd_write(rsm, V1, ci, tid);
}

// ---------------------------------------------------------------------------
// FUSED inverse(U,O) + combine + forward transform of h (all nodes).
// Per-channel block. Root (n==0): writes out, no transform.
// ---------------------------------------------------------------------------
__global__ void inv_combine_kernel(int n, const float* __restrict__ ub,
                                   const float* __restrict__ ob,
                                   float* __restrict__ outroot,
                                   __nv_bfloat16* __restrict__ V2) {
    __shared__ float hsm[66][67];
    int c = blockIdx.x, tid = threadIdx.x;
    bool haskids = g_childcount[n] > 0;
    for (int i = tid; i < 66 * 67; i += 256) (&hsm[0][0])[i] = 0.f;
    __syncthreads();
    int t = tid, ty = t >> 4, tx = t & 15;
    float u16[4][4], o16[4][4];
    if (haskids) {
        inv_read(g_m, c, t, u16);
        inv_read(g_m + M_STRIDE, c, t, o16);
    }
    float tu9[9], to9[9];
#pragma unroll
    for (int k = 0; k < 9; k++) {
        tu9[k] = g_t[((1 * NND + n) * 9 + k) * CHN + c];
        to9[k] = g_t[((2 * NND + n) * 9 + k) * CHN + c];
    }
    float ubc = ub[c], obc = ob[c];
    const float* Gu = g_buf + 2 * CHW + (size_t)c * HW;
    const float* Go = g_buf + 3 * CHW + (size_t)c * HW;
    const float* CS = g_buf + 4 * CHW + (size_t)c * HW;
    float* hpl = (n == 0) ? (outroot + (size_t)c * HW)
                          : (g_buf + (size_t)(8 + n) * CHW + (size_t)c * HW);
#pragma unroll
    for (int i = 0; i < 4; i++) {
#pragma unroll
        for (int j = 0; j < 4; j++) {
            int y = 4 * ty + i, x = 4 * tx + j;
            int p = y * WW + x;
            int ky0 = (y == 0), ky1 = 2 - (y == HH - 1);
            int kx0 = (x == 0), kx1 = 2 - (x == WW - 1);
            float cu = 0.f, co = 0.f;
            for (int ky = ky0; ky <= ky1; ky++)
                for (int kx = kx0; kx <= kx1; kx++) {
                    cu += tu9[ky * 3 + kx];
                    co += to9[ky * 3 + kx];
                }
            float uacc = haskids ? u16[i][j] : 0.f;
            float oacc = haskids ? o16[i][j] : 0.f;
            float cs   = haskids ? CS[p] : 0.f;
            float z  = sigm(Gu[p] + ubc + cu + uacc);
            float ri = tanhf(Go[p] + obc + co + oacc);
            float h = (1.f - z) * ri + z * cs;
            hpl[p] = h;
            hsm[y + 1][x + 1] = h;
        }
    }
    if (n > 0) {
        __syncthreads();
        fwd_write(hsm, V2, c, t);
    }
}

// ---------------------------------------------------------------------------
// Winograd GEMM: per j, M_j[co][tile] = U_j[co][ci] * V_j[ci][tile]
// bf16 3-split, fp32 accum. K=512 -> 24 stages of 64.
// CTA 128co x 128tile, 4 warps (2m x 2n). grid (2, 4, 36*nconv).
// ---------------------------------------------------------------------------
#define WG_SMEM 98304   // 3 x (A 16KB + B 16KB)

__device__ __forceinline__ void wg_issue_stage(
    int s, uint32_t sA, int tid, int tileB, int coB, int part, int j,
    const __nv_bfloat16* V) {
    int s3 = s >> 3;
    int cb = (s & 7) << 6;
    int wsplit = (s3 == 1) ? 1 : 0;
    int xsplit = (s3 == 2) ? 1 : 0;
    const __nv_bfloat16* Abase =
        g_uw + ((((size_t)(part * 2 + wsplit) * NJ + j) * 512 + coB) << 9) + cb;
    const __nv_bfloat16* Bbase =
        V + (((size_t)(xsplit * NJ + j) * 512 + cb) * NT2) + tileB;
    uint32_t slot = sA + (s % 3) * 32768;
#pragma unroll
    for (int it = 0; it < 8; it++) {
        int i = tid + it * 128;
        int o = i >> 3, q = i & 7;
        cp16(slot + SWZ(o * 128 + q * 16), Abase + ((size_t)o << 9) + q * 8);
    }
#pragma unroll
    for (int it = 0; it < 8; it++) {
        int i = tid + it * 128;
        int k = i >> 4, cc = i & 15;
        cp16(slot + 16384 + k * 256 + ((cc ^ (k & 7)) << 4),
             Bbase + (size_t)k * NT2 + cc * 8);
    }
    asm volatile("cp.async.commit_group;" ::: "memory");
}

__global__ __launch_bounds__(128)
void wg_gemm_kernel(const __nv_bfloat16* __restrict__ V0, int p0,
                    const __nv_bfloat16* __restrict__ V1, int p1,
                    const __nv_bfloat16* __restrict__ V2, int p2,
                    float* __restrict__ M0, float* __restrict__ M1,
                    float* __restrict__ M2, int flag_n) {
    if (flag_n >= 0 && g_childcount[flag_n] == 0) return;
    extern __shared__ char smem[];
    uint32_t sA = smem_u32(smem);
    int which = blockIdx.z / NJ;
    int j = blockIdx.z - which * NJ;
    const __nv_bfloat16* V = (which == 0) ? V0 : (which == 1) ? V1 : V2;
    int part = (which == 0) ? p0 : (which == 1) ? p1 : p2;
    float* M = (which == 0) ? M0 : (which == 1) ? M1 : M2;

    int tid = threadIdx.x;
    int wid = tid >> 5, lane = tid & 31;
    int tileB = blockIdx.x * 128;
    int coB   = blockIdx.y * 128;
    int wm = wid >> 1;
    int wn = wid & 1;

    float acc[4][8][4];
#pragma unroll
    for (int a = 0; a < 4; a++)
#pragma unroll
        for (int b = 0; b < 8; b++)
#pragma unroll
            for (int c = 0; c < 4; c++) acc[a][b][c] = 0.f;

    wg_issue_stage(0, sA, tid, tileB, coB, part, j, V);
    wg_issue_stage(1, sA, tid, tileB, coB, part, j, V);

    for (int s = 0; s < 24; s++) {
        asm volatile("cp.async.wait_group 1;" ::: "memory");
        __syncthreads();
        if (s + 2 < 24)
            wg_issue_stage(s + 2, sA, tid, tileB, coB, part, j, V);
        uint32_t Ab = sA + (s % 3) * 32768;
        uint32_t Bb = Ab + 16384;
#pragma unroll
        for (int ks = 0; ks < 4; ks++) {
            uint32_t afr[4][4];
#pragma unroll
            for (int mi = 0; mi < 4; mi++) {
                int row = wm * 64 + mi * 16 + (lane & 15);
                int k16 = ks * 2 + (lane >> 4);
                ldm4(afr[mi], Ab + SWZ(row * 128 + k16 * 16));
            }
            uint32_t bfr[4][4];
#pragma unroll
            for (int ng = 0; ng < 4; ng++) {
                int krow = ks * 16 + (lane & 7) + (((lane >> 3) & 1) << 3);
                int cc   = ((wn * 64 + ng * 16) >> 3) + (lane >> 4);
                ldm4t(bfr[ng], Bb + krow * 256 + ((cc ^ (krow & 7)) << 4));
            }
#pragma unroll
            for (int mi = 0; mi < 4; mi++)
#pragma unroll
                for (int ng = 0; ng < 4; ng++) {
                    mma_bf(acc[mi][ng * 2 + 0], afr[mi], bfr[ng][0], bfr[ng][1]);
                    mma_bf(acc[mi][ng * 2 + 1], afr[mi], bfr[ng][2], bfr[ng][3]);
                }
        }
        __syncthreads();
    }

#pragma unroll
    for (int mi = 0; mi < 4; mi++) {
        int row0 = coB + wm * 64 + mi * 16 + (lane >> 2);
        float* mp0 = M + ((size_t)j * 512 + row0) * NT2 + tileB;
#pragma unroll
        for (int nj = 0; nj < 8; nj++) {
            int col = wn * 64 + nj * 8 + (lane & 3) * 2;
            *reinterpret_cast<float2*>(mp0 + col) =
                make_float2(acc[mi][nj][0], acc[mi][nj][1]);
            *reinterpret_cast<float2*>(mp0 + 8 * NT2 + col) =
                make_float2(acc[mi][nj][2], acc[mi][nj][3]);
        }
    }
}

// ---------------------------------------------------------------------------
// mconv 1x1 GEMM via bf16 3-split mma: out[co][px] = mw[:, :512] @ vis
// B = g_vs [split][ci][px] (row stride HW). grid (32 pxB, 4 coB).
// ---------------------------------------------------------------------------
__device__ __forceinline__ void mc_issue_stage(int s, uint32_t sA, int tid,
                                               int pxB, int coB) {
    int s3 = s >> 3;
    int cb = (s & 7) << 6;
    int wsplit = (s3 == 1) ? 1 : 0;
    int xsplit = (s3 == 2) ? 1 : 0;
    const __nv_bfloat16* Abase = g_mwsp + (size_t)wsplit * 262144 + (coB << 9) + cb;
    const __nv_bfloat16* Bbase = g_vs + (size_t)xsplit * CHW + (size_t)cb * HW + pxB;
    uint32_t slot = sA + (s % 3) * 32768;
#pragma unroll
    for (int it = 0; it < 8; it++) {
        int i = tid + it * 128;
        int o = i >> 3, q = i & 7;
        cp16(slot + SWZ(o * 128 + q * 16), Abase + ((size_t)o << 9) + q * 8);
    }
#pragma unroll
    for (int it = 0; it < 8; it++) {
        int i = tid + it * 128;
        int k = i >> 4, cc = i & 15;
        cp16(slot + 16384 + k * 256 + ((cc ^ (k & 7)) << 4),
             Bbase + (size_t)k * HW + cc * 8);
    }
    asm volatile("cp.async.commit_group;" ::: "memory");
}

__global__ __launch_bounds__(128)
void mc_gemm_kernel(float* __restrict__ out) {
    extern __shared__ char smem[];
    uint32_t sA = smem_u32(smem);
    int tid = threadIdx.x;
    int wid = tid >> 5, lane = tid & 31;
    int pxB = blockIdx.x * 128;
    int coB = blockIdx.y * 128;
    int wm = wid >> 1;
    int wn = wid & 1;

    float acc[4][8][4];
#pragma unroll
    for (int a = 0; a < 4; a++)
#pragma unroll
        for (int b = 0; b < 8; b++)
#pragma unroll
            for (int c = 0; c < 4; c++) acc[a][b][c] = 0.f;

    mc_issue_stage(0, sA, tid, pxB, coB);
    mc_issue_stage(1, sA, tid, pxB, coB);

    for (int s = 0; s < 24; s++) {
        asm volatile("cp.async.wait_group 1;" ::: "memory");
        __syncthreads();
        if (s + 2 < 24)
            mc_issue_stage(s + 2, sA, tid, pxB, coB);
        uint32_t Ab = sA + (s % 3) * 32768;
        uint32_t Bb = Ab + 16384;
#pragma unroll
        for (int ks = 0; ks < 4; ks++) {
            uint32_t afr[4][4];
#pragma unroll
            for (int mi = 0; mi < 4; mi++) {
                int row = wm * 64 + mi * 16 + (lane & 15);
                int k16 = ks * 2 + (lane >> 4);
                ldm4(afr[mi], Ab + SWZ(row * 128 + k16 * 16));
            }
            uint32_t bfr[4][4];
#pragma unroll
            for (int ng = 0; ng < 4; ng++) {
                int krow = ks * 16 + (lane & 7) + (((lane >> 3) & 1) << 3);
                int cc   = ((wn * 64 + ng * 16) >> 3) + (lane >> 4);
                ldm4t(bfr[ng], Bb + krow * 256 + ((cc ^ (krow & 7)) << 4));
            }
#pragma unroll
            for (int mi = 0; mi < 4; mi++)
#pragma unroll
                for (int ng = 0; ng < 4; ng++) {
                    mma_bf(acc[mi][ng * 2 + 0], afr[mi], bfr[ng][0], bfr[ng][1]);
                    mma_bf(acc[mi][ng * 2 + 1], afr[mi], bfr[ng][2], bfr[ng][3]);
                }
        }
        __syncthreads();
    }

#pragma unroll
    for (int mi = 0; mi < 4; mi++) {
        int row0 = coB + wm * 64 + mi * 16 + (lane >> 2);
        float* op = out + (size_t)row0 * HW + pxB;
#pragma unroll
        for (int nj = 0; nj < 8; nj++) {
            int col = wn * 64 + nj * 8 + (lane & 3) * 2;
            *reinterpret_cast<float2*>(op + col) =
                make_float2(acc[mi][nj][0], acc[mi][nj][1]);
            *reinterpret_cast<float2*>(op + 8 * HW + col) =
                make_float2(acc[mi][nj][2], acc[mi][nj][3]);
        }
    }
}

// ---------------------------------------------------------------------------
// Plain inverse transform (initial Gr/Gu/Go convs)
// ---------------------------------------------------------------------------
__global__ void wg_inv_kernel(float* __restrict__ D0, float* __restrict__ D1,
                              float* __restrict__ D2) {
    int conv = blockIdx.y;
    const float* M = g_m + (size_t)conv * M_STRIDE;
    float* D = (conv == 0) ? D0 : (conv == 1) ? D1 : D2;
    int e = blockIdx.x * 256 + threadIdx.x;
    int co = e >> 8, t = e & (NT2 - 1);
    float y16[4][4];
    inv_read(M, co, t, y16);
    int ty = t >> 4, tx = t & 15;
    float* op = D + (size_t)co * HW + (4 * ty) * WW + 4 * tx;
#pragma unroll
    for (int i = 0; i < 4; i++)
        *reinterpret_cast<float4*>(op + i * WW) =
            make_float4(y16[i][0], y16[i][1], y16[i][2], y16[i][3]);
}

// ---------------------------------------------------------------------------
extern "C" void kernel_launch(void* const* d_in, const int* in_sizes, int n_in,
                              void* d_out, int out_size) {
    const float* vis  = (const float*)d_in[0];
    const float* lang = (const float*)d_in[1];
    const int*   adj  = (const int*)d_in[2];
    const float* mw   = (const float*)d_in[3];
    const float* mb   = (const float*)d_in[4];
    const float* rw   = (const float*)d_in[5];
    const float* rb   = (const float*)d_in[6];
    const float* uw   = (const float*)d_in[7];
    const float* ub   = (const float*)d_in[8];
    const float* ow   = (const float*)d_in[9];
    const float* ob   = (const float*)d_in[10];
    float* out = (float*)d_out;

    float* buf = nullptr;
    cudaGetSymbolAddress((void**)&buf, g_buf);
    __nv_bfloat16* wv = nullptr;
    cudaGetSymbolAddress((void**)&wv, g_wV);
    float* m = nullptr;
    cudaGetSymbolAddress((void**)&m, g_m);
    float* mr = nullptr;
    cudaGetSymbolAddress((void**)&mr, g_mr);
    __nv_bfloat16* V0 = wv;
    __nv_bfloat16* V1 = wv + VT_STRIDE;
    __nv_bfloat16* V2 = wv + 2 * VT_STRIDE;

    static bool attr_done = false;
    if (!attr_done) {
        cudaFuncSetAttribute(wg_gemm_kernel,
                             cudaFuncAttributeMaxDynamicSharedMemorySize, WG_SMEM);
        cudaFuncSetAttribute(mc_gemm_kernel,
                             cudaFuncAttributeMaxDynamicSharedMemorySize, WG_SMEM);
        attr_done = true;
    }

    dim3 wgrid1(2, 4, NJ);               // winograd gemm, 1 conv
    dim3 wgrid2(2, 4, 2 * NJ);           // 2 convs
    dim3 wgrid3(2, 4, 3 * NJ);           // 3 convs
    dim3 mcg(32, 4);                     // mconv gemm
    dim3 inv3(512, 3);

    prep_kernel<<<1, 32>>>(adj);
    langbias_kernel<<<40, 256>>>(lang, mw, mb);
    tapconst_kernel<<<54, 256>>>(rw, uw, ow);
    wg_wprep_kernel<<<6144, 256>>>(rw, uw, ow);
    vis_split_kernel<<<8192, 256>>>(vis);
    mw_split_kernel<<<1024, 256>>>(mw);

    // V-plane = conv1x1(vis, mconv_w[:, :512]) via split-bf16 mma
    mc_gemm_kernel<<<mcg, 128, WG_SMEM>>>(buf);

    // shared convs of V (x-part weights of the 3 gates): Gr, Gu, Go
    wg_itrans_kernel<<<512, 256>>>(buf, V0);
    wg_gemm_kernel<<<wgrid3, 128, WG_SMEM>>>(V0, 0, V0, 2, V0, 4,
                                             m, m + M_STRIDE, m + 2 * M_STRIDE, -1);
    wg_inv_kernel<<<inv3, 256>>>(buf + 1 * CHW, buf + 2 * CHW, buf + 3 * CHW);

    // nodes in decreasing index = valid topological order (parent(i) < i)
    for (int n = NND - 1; n >= 0; n--) {
        // fused gather (+R inverse) + forward transforms of cs, rh (skips on leaf)
        gather_itrans_kernel<<<512, 256>>>(n, rb, V0, V1);
        // U = conv(cs, Wu_h), O = conv(rh, Wo_h) (skips on leaf)
        wg_gemm_kernel<<<wgrid2, 128, WG_SMEM>>>(V0, 3, V1, 5, V1, 5,
                                                 m, m + M_STRIDE, m + 2 * M_STRIDE, n);
        // fused inverse(U,O) + combine (+ forward transform of h when n>0)
        inv_combine_kernel<<<512, 256>>>(n, ub, ob, out, V2);
        if (n > 0)  // R[n] (Winograd domain, inverse deferred to parent's gather)
            wg_gemm_kernel<<<wgrid1, 128, WG_SMEM>>>(
                V2, 1, V2, 1, V2, 1,
                mr + (size_t)n * M_STRIDE, nullptr, nullptr, -1);
    }
}